// round 15
// baseline (speedup 1.0000x reference)
#include <cuda_runtime.h>
#include <cuda_fp16.h>
#include <cstdint>

#define NN 100000
#define EE 1600000
#define MINN 1e-15f
#define MAXN ((float)(1.0 - 1e-5))
#define SCAN_BLOCKS 98
#define NODE_TILES ((NN + 63) / 64)   // 64 nodes per tile (8 per warp)
#define PERSIST_BLOCKS 296            // 2 per SM on 148 SMs (co-resident)

// ---------------- scratch ----------------
__device__ __align__(16) __half g_t[(size_t)NN * 64];
__device__ __align__(16) __half g_t2[(size_t)NN * 64];
__device__ int g_col[EE];
__device__ int g_cnt[NN];          // zero at load; re-zeroed by phase-C tail
__device__ int g_off[NN + 1];
__device__ int g_cursor[NN];
__device__ int g_bsum[SCAN_BLOCKS];
__device__ int g_scan_done;        // zero at load; reset by nodeBC
__device__ unsigned g_ticket;      // monotonic grid-barrier counter

// ---------------- fast math (args nonnegative) ----------------
__device__ __forceinline__ float fast_tanh(float x) {
    float e = __expf(-2.f * x);
    return __fdividef(1.f - e, 1.f + e);
}
__device__ __forceinline__ float fast_atanh(float x) {
    x = fminf(x, MAXN);
    return 0.5f * __logf(__fdividef(1.f + x, 1.f - x));
}

// reduce v[8] across warp -> every lane gets total of slot (j&7). 9 SHFL.
__device__ __forceinline__ float rsum8(const float v[8], int j) {
    bool p1 = j & 1;
    float a[4];
#pragma unroll
    for (int i = 0; i < 4; i++) {
        float m = p1 ? v[2 * i + 1] : v[2 * i];
        float o = p1 ? v[2 * i] : v[2 * i + 1];
        a[i] = m + __shfl_xor_sync(0xffffffffu, o, 1);
    }
    bool p2 = j & 2;
    float b0, b1;
    {
        float m = p2 ? a[1] : a[0], o = p2 ? a[0] : a[1];
        b0 = m + __shfl_xor_sync(0xffffffffu, o, 2);
    }
    {
        float m = p2 ? a[3] : a[2], o = p2 ? a[2] : a[3];
        b1 = m + __shfl_xor_sync(0xffffffffu, o, 2);
    }
    bool p4 = j & 4;
    float m = p4 ? b1 : b0, o = p4 ? b0 : b1;
    float c = m + __shfl_xor_sync(0xffffffffu, o, 4);
    c += __shfl_xor_sync(0xffffffffu, c, 8);
    c += __shfl_xor_sync(0xffffffffu, c, 16);
    return c;
}

// two independent rsum8's interleaved (half the exposed shfl-chain depth)
__device__ __forceinline__ void rsum8x2(const float va[8], const float vb[8],
                                        int j, float& ra, float& rb) {
    bool p1 = j & 1;
    float A[4], B[4];
#pragma unroll
    for (int i = 0; i < 4; i++) {
        float am = p1 ? va[2 * i + 1] : va[2 * i];
        float ao = p1 ? va[2 * i] : va[2 * i + 1];
        float bm = p1 ? vb[2 * i + 1] : vb[2 * i];
        float bo = p1 ? vb[2 * i] : vb[2 * i + 1];
        A[i] = am + __shfl_xor_sync(0xffffffffu, ao, 1);
        B[i] = bm + __shfl_xor_sync(0xffffffffu, bo, 1);
    }
    bool p2 = j & 2;
    float a0, a1, b0, b1;
    { float m = p2 ? A[1] : A[0], o = p2 ? A[0] : A[1]; a0 = m + __shfl_xor_sync(0xffffffffu, o, 2); }
    { float m = p2 ? B[1] : B[0], o = p2 ? B[0] : B[1]; b0 = m + __shfl_xor_sync(0xffffffffu, o, 2); }
    { float m = p2 ? A[3] : A[2], o = p2 ? A[2] : A[3]; a1 = m + __shfl_xor_sync(0xffffffffu, o, 2); }
    { float m = p2 ? B[3] : B[2], o = p2 ? B[2] : B[3]; b1 = m + __shfl_xor_sync(0xffffffffu, o, 2); }
    bool p4 = j & 4;
    { float m = p4 ? a1 : a0, o = p4 ? a0 : a1; ra = m + __shfl_xor_sync(0xffffffffu, o, 4); }
    { float m = p4 ? b1 : b0, o = p4 ? b0 : b1; rb = m + __shfl_xor_sync(0xffffffffu, o, 4); }
    ra += __shfl_xor_sync(0xffffffffu, ra, 8);
    rb += __shfl_xor_sync(0xffffffffu, rb, 8);
    ra += __shfl_xor_sync(0xffffffffu, ra, 16);
    rb += __shfl_xor_sync(0xffffffffu, rb, 16);
}

__device__ __forceinline__ void bcast8(float v, float o[8]) {
#pragma unroll
    for (int q = 0; q < 8; q++) o[q] = __shfl_sync(0xffffffffu, v, q);
}

// stage 8 nodes: xs[j*10 + q] = float2(h0[q], h1[q]) (80B padded rows)
__device__ __forceinline__ void stage_x8(float2* xs, const float h0[8],
                                         const float h1[8], int j) {
    __syncwarp();
#pragma unroll
    for (int q = 0; q < 8; q++) xs[j * 10 + q] = make_float2(h0[q], h1[q]);
    __syncwarp();
}

// 64x64 matvec block: raw M for 8 nodes, plain scalar FFMA.
// Lane j owns output comps (2j,2j+1).
// Wf[t*32+j] = (W[2j][2t], W[2j][2t+1], W[2j+1][2t], W[2j+1][2t+1])
__device__ __forceinline__ void fma_block64(const float4* __restrict__ Wf,
                                            const float2* xs, int j,
                                            float m0[8], float m1[8]) {
#pragma unroll
    for (int q = 0; q < 8; q++) { m0[q] = 0.f; m1[q] = 0.f; }
#pragma unroll
    for (int t = 0; t < 32; t++) {
        float4 wv = Wf[t * 32 + j];
        const float4* xt = (const float4*)(xs + t * 10);
        float4 xA = xt[0], xB = xt[1], xC = xt[2], xD = xt[3];
        m0[0] = fmaf(xA.x, wv.x, fmaf(xA.y, wv.y, m0[0]));
        m1[0] = fmaf(xA.x, wv.z, fmaf(xA.y, wv.w, m1[0]));
        m0[1] = fmaf(xA.z, wv.x, fmaf(xA.w, wv.y, m0[1]));
        m1[1] = fmaf(xA.z, wv.z, fmaf(xA.w, wv.w, m1[1]));
        m0[2] = fmaf(xB.x, wv.x, fmaf(xB.y, wv.y, m0[2]));
        m1[2] = fmaf(xB.x, wv.z, fmaf(xB.y, wv.w, m1[2]));
        m0[3] = fmaf(xB.z, wv.x, fmaf(xB.w, wv.y, m0[3]));
        m1[3] = fmaf(xB.z, wv.z, fmaf(xB.w, wv.w, m1[3]));
        m0[4] = fmaf(xC.x, wv.x, fmaf(xC.y, wv.y, m0[4]));
        m1[4] = fmaf(xC.x, wv.z, fmaf(xC.y, wv.w, m1[4]));
        m0[5] = fmaf(xC.z, wv.x, fmaf(xC.w, wv.y, m0[5]));
        m1[5] = fmaf(xC.z, wv.z, fmaf(xC.w, wv.w, m1[5]));
        m0[6] = fmaf(xD.x, wv.x, fmaf(xD.y, wv.y, m0[6]));
        m1[6] = fmaf(xD.x, wv.z, fmaf(xD.y, wv.w, m1[6]));
        m0[7] = fmaf(xD.z, wv.x, fmaf(xD.w, wv.y, m0[7]));
        m1[7] = fmaf(xD.z, wv.z, fmaf(xD.w, wv.w, m1[7]));
    }
}

// post-matvec scalar chain -> broadcast coeffs AA,BB (out = AA*M + BB*e).
__device__ __forceinline__ void layer_post(
    const float m0[8], const float m1[8], float c, float ratio,
    float2 ev, float ebn2, bool with_sl, float AA[8], float BB[8], int j) {
    float s2[8], d[8];
#pragma unroll
    for (int q = 0; q < 8; q++) {
        s2[q] = m0[q] * m0[q] + m1[q] * m1[q];
        d[q] = m0[q] * ev.x + m1[q] * ev.y;
    }
    float s2s, ds;
    rsum8x2(s2, d, j, s2s, ds);
    float ml = c * sqrtf(s2s);
    float mx = fmaxf(ml, MINN);
    float r = fast_tanh(mx * ratio);
    float sc = c * __fdividef(r, mx);          // applies to raw M
    float n1 = fmaxf(r * __fdividef(ml, mx), MINN);
    if (n1 > MAXN) { sc *= __fdividef(MAXN, n1); n1 = MAXN; }
    float xyv = sc * ds;
    float x2 = n1 * n1;
    float c1 = 1.f + 2.f * xyv + ebn2;
    float c2 = 1.f - x2;
    float iv = __fdividef(1.f, fmaxf(1.f + 2.f * xyv + x2 * ebn2, MINN));
    float q2v = iv * iv * (c1 * c1 * x2 + 2.f * c1 * c2 * xyv + c2 * c2 * ebn2);
    float nf = fmaxf(sqrtf(q2v), MINN);
    float ps = 1.f;
    if (nf > MAXN) { ps = __fdividef(MAXN, nf); nf = MAXN; }
    float sl = with_sl ? __fdividef(fast_atanh(nf), nf) : 1.f;
    float A = ps * iv * c1 * sc * sl;
    float B = ps * iv * c2 * sl;
    bcast8(A, AA);
    bcast8(B, BB);
}

// act prelude for the NEXT layer from staged-u t2 partials.
__device__ __forceinline__ void act_pre(const float t2[8], int j,
                                        float& c, float& ratio) {
    float t2s = rsum8(t2, j);
    float tn = sqrtf(t2s);
    float tc = fmaxf(tn, MINN);
    float se = __fdividef(fast_tanh(tc), tc);
    float nn = fmaxf(se * tn, MINN);
    if (nn > MAXN) { se *= __fdividef(MAXN, nn); nn = MAXN; }
    c = se;
    ratio = __fdividef(fast_atanh(nn), nn);
}

// relu(A*M + B*e) -> unscaled u staged + t2 partials
__device__ __forceinline__ void relu_stage(const float m0[8], const float m1[8],
                                           const float AA[8], const float BB[8],
                                           float2 ev, float2* xs, int j, float t2[8]) {
#pragma unroll
    for (int q = 0; q < 8; q++) {
        float u0 = fmaxf(AA[q] * m0[q] + BB[q] * ev.x, 0.f);
        float u1 = fmaxf(AA[q] * m1[q] + BB[q] * ev.y, 0.f);
        t2[q] = u0 * u0 + u1 * u1;
        xs[j * 10 + q] = make_float2(u0, u1);
    }
    __syncwarp();
}

// bias -> eb = expmap0(b), |eb|^2, one warp
__device__ __forceinline__ void compute_eb64(const float* __restrict__ b,
                                             float* eb, float* ebn2, int j) {
    float v0 = b[j], v1 = b[32 + j];
    float s2 = v0 * v0 + v1 * v1;
#pragma unroll
    for (int o = 16; o > 0; o >>= 1) s2 += __shfl_xor_sync(0xffffffffu, s2, o);
    float bn = sqrtf(s2), bc = fmaxf(bn, MINN);
    float se = __fdividef(fast_tanh(bc), bc);
    eb[j] = v0 * se;
    eb[32 + j] = v1 * se;
    if (j == 0) *ebn2 = (se * bn) * (se * bn);
}

// CSR gather for one node; lane j sums comps (2j,2j+1) via half2 (4B/lane/nbr)
__device__ __forceinline__ void csr_agg(const __half* __restrict__ tsrc, int node,
                                        int j, float& o0, float& o1, int& deg) {
    const __half2* tp = (const __half2*)tsrc;
    int s = g_off[node], e = g_off[node + 1];
    deg = e - s;
    float a0 = 0.f, a1 = 0.f, b0 = 0.f, b1 = 0.f;
    for (int base = s; base < e; base += 32) {
        int nh = min(32, e - base);
        int idx = (j < nh) ? g_col[base + j] : 0;
        int t = 0;
        for (; t + 8 <= nh; t += 8) {
#pragma unroll
            for (int u = 0; u < 8; u += 2) {
                int sa = __shfl_sync(0xffffffffu, idx, t + u);
                int sb = __shfl_sync(0xffffffffu, idx, t + u + 1);
                float2 va = __half22float2(__ldg(tp + (size_t)sa * 32 + j));
                float2 vb = __half22float2(__ldg(tp + (size_t)sb * 32 + j));
                a0 += va.x; a1 += va.y;
                b0 += vb.x; b1 += vb.y;
            }
        }
        for (; t < nh; t++) {
            int sx = __shfl_sync(0xffffffffu, idx, t);
            float2 v = __half22float2(__ldg(tp + (size_t)sx * 32 + j));
            a0 += v.x; a1 += v.y;
        }
    }
    o0 = a0 + b0; o1 = a1 + b1;
}

// agg mean + (expmap0,proj,logmap0 folded) + relu -> unscaled u staged + t2
__device__ __forceinline__ void agg_relu_stage(const __half* __restrict__ tsrc,
                                               int iBase, int j, float2* xs,
                                               float t2[8]) {
    float h0[8], h1[8], n2[8];
#pragma unroll
    for (int q = 0; q < 8; q++) {
        int node = min(iBase + q, NN - 1);
        int deg;
        float a0, a1;
        csr_agg(tsrc, node, j, a0, a1, deg);
        float inv = __fdividef(1.f, fmaxf((float)deg, 1.f));
        h0[q] = a0 * inv;
        h1[q] = a1 * inv;
        n2[q] = h0[q] * h0[q] + h1[q] * h1[q];
    }
    float n2s = rsum8(n2, j);
    float un = sqrtf(n2s);
    float uc = fmaxf(un, MINN);
    float se = __fdividef(fast_tanh(uc), uc);
    float nn = fmaxf(se * un, MINN);
    if (nn > MAXN) { se *= __fdividef(MAXN, nn); nn = MAXN; }
    float comb = se * __fdividef(fast_atanh(nn), nn);
    float CB[8];
    bcast8(comb, CB);
#pragma unroll
    for (int q = 0; q < 8; q++) {
        float u0 = fmaxf(h0[q] * CB[q], 0.f);
        float u1 = fmaxf(h1[q] * CB[q], 0.f);
        t2[q] = u0 * u0 + u1 * u1;
        xs[j * 10 + q] = make_float2(u0, u1);
    }
    __syncwarp();
}

// load weights: Wf[t*32+j] = (W[2j][2t], W[2j][2t+1], W[2j+1][2t], W[2j+1][2t+1])
__device__ __forceinline__ void load_Wq(float4* Wf, const float* __restrict__ W,
                                        int K, int tid) {
    for (int i = tid; i < 1024; i += 256) {
        int t = i >> 5, jj = i & 31;
        int k0 = 2 * t, k1 = 2 * t + 1;
        int r0 = 2 * jj, r1 = 2 * jj + 1;
        float4 v;
        v.x = W[r0 * K + k0];
        v.y = (k1 < K) ? W[r0 * K + k1] : 0.f;
        v.z = W[r1 * K + k0];
        v.w = (k1 < K) ? W[r1 * K + k1] : 0.f;
        Wf[t * 32 + jj] = v;
    }
}

// block-local edge dtype detection
__device__ __forceinline__ int local_idx64(const int* __restrict__ e32, int* s_flag) {
    if (threadIdx.x == 0) *s_flag = 1;
    __syncthreads();
    if (threadIdx.x < 256 && e32[2 * threadIdx.x + 1] != 0) *s_flag = 0;
    __syncthreads();
    return *s_flag;
}

// monotonic ticket grid-barrier (all PERSIST_BLOCKS co-resident by occupancy)
__device__ __forceinline__ void grid_barrier() {
    __syncthreads();
    if (threadIdx.x == 0) {
        __threadfence();
        unsigned v = atomicAdd(&g_ticket, 1u);
        unsigned target = (v / PERSIST_BLOCKS + 1u) * PERSIST_BLOCKS;
        while (*(volatile unsigned*)&g_ticket < target) {}
        __threadfence();
    }
    __syncthreads();
}

// ---------------- kernel A: poincare + layers 1..4 + logmap -> g_t ----------
__global__ void __launch_bounds__(256, 2) nodeA_kernel(
    const float* __restrict__ x,
    const float* __restrict__ W1, const float* __restrict__ b1,
    const float* __restrict__ W2, const float* __restrict__ b2,
    const float* __restrict__ W3, const float* __restrict__ b3,
    const float* __restrict__ W4, const float* __restrict__ b4) {
    extern __shared__ unsigned char smem_raw[];
    float4* Wf = (float4*)smem_raw;              // 4*1024 float4 = 64KB
    float2* xall = (float2*)(Wf + 4 * 1024);     // 8 warps * 320 float2 = 20KB
    float* eb = (float*)(xall + 8 * 320);
    float* ebn2 = eb + 256;
    int tid = threadIdx.x;

    load_Wq(Wf,        W1, 63, tid);
    load_Wq(Wf + 1024, W2, 64, tid);
    load_Wq(Wf + 2048, W3, 64, tid);
    load_Wq(Wf + 3072, W4, 64, tid);
    int w = tid >> 5, j = tid & 31;
    if (w < 4) {
        const float* bp[4] = {b1, b2, b3, b4};
        compute_eb64(bp[w], eb + w * 64, ebn2 + w, j);
    }
    __syncthreads();

    float2* xs = xall + w * 320;

    for (int tile = blockIdx.x; tile < NODE_TILES; tile += gridDim.x) {
        int iBase = tile * 64 + w * 8;
        float t2[8], m0[8], m1[8], AA[8], BB[8];
        float c, ratio;

        // poincare map (raw; proj scale deferred into c)
        {
            float h0[8], h1[8], n2[8];
#pragma unroll
            for (int q = 0; q < 8; q++) {
                const float* xp = x + (size_t)min(iBase + q, NN - 1) * 64;
                float inv = __fdividef(1.f, xp[0] + 1.f);
                h0[q] = xp[1 + 2 * j] * inv;
                h1[q] = (j < 31) ? xp[2 + 2 * j] * inv : 0.f;
                n2[q] = h0[q] * h0[q] + h1[q] * h1[q];
            }
            stage_x8(xs, h0, h1, j);
            float n2s = rsum8(n2, j);
            float nf = fmaxf(sqrtf(n2s), MINN);
            float ps = 1.f;
            if (nf > MAXN) { ps = __fdividef(MAXN, nf); nf = MAXN; }
            c = ps;
            ratio = __fdividef(fast_atanh(nf), nf);
        }

        float2 ev;
        ev = *(const float2*)(eb + 2 * j);
        fma_block64(Wf, xs, j, m0, m1);
        layer_post(m0, m1, c, ratio, ev, ebn2[0], true, AA, BB, j);
        relu_stage(m0, m1, AA, BB, ev, xs, j, t2);
        act_pre(t2, j, c, ratio);

        ev = *(const float2*)(eb + 64 + 2 * j);
        fma_block64(Wf + 1024, xs, j, m0, m1);
        layer_post(m0, m1, c, ratio, ev, ebn2[1], true, AA, BB, j);
        relu_stage(m0, m1, AA, BB, ev, xs, j, t2);
        act_pre(t2, j, c, ratio);

        ev = *(const float2*)(eb + 128 + 2 * j);
        fma_block64(Wf + 2048, xs, j, m0, m1);
        layer_post(m0, m1, c, ratio, ev, ebn2[2], true, AA, BB, j);
        relu_stage(m0, m1, AA, BB, ev, xs, j, t2);
        act_pre(t2, j, c, ratio);

        ev = *(const float2*)(eb + 192 + 2 * j);
        fma_block64(Wf + 3072, xs, j, m0, m1);
        layer_post(m0, m1, c, ratio, ev, ebn2[3], true, AA, BB, j);
#pragma unroll
        for (int q = 0; q < 8; q++) {
            if (iBase + q < NN) {
                float v0 = AA[q] * m0[q] + BB[q] * ev.x;
                float v1 = AA[q] * m1[q] + BB[q] * ev.y;
                *((__half2*)g_t + (size_t)(iBase + q) * 32 + j) =
                    __floats2half2_rn(v0, v1);
            }
        }
    }
}

// ---------------- kernel BC: agg+act+L5 -> g_t2 | barrier | agg+act+L6 -> out
__global__ void __launch_bounds__(256, 2) nodeBC_kernel(
    const float* __restrict__ W5, const float* __restrict__ b5,
    const float* __restrict__ W6, const float* __restrict__ b6,
    float* __restrict__ out) {
    extern __shared__ unsigned char smem_raw[];
    float4* Wf = (float4*)smem_raw;              // 1024 float4 = 16KB (W5)
    float2* W6f = (float2*)(Wf + 1024);          // 1024 float2 = 8KB  (W6)
    float2* xall = W6f + 1024;                   // 8 * 320 float2 = 20KB
    float* eb5 = (float*)(xall + 8 * 320);       // 64
    float* ebn25 = eb5 + 64;                     // 1
    float* eb6 = ebn25 + 1;                      // 32
    float* ebn26 = eb6 + 32;                     // 1
    int tid = threadIdx.x;

    load_Wq(Wf, W5, 64, tid);
    for (int i = tid; i < 1024; i += 256) {
        int t = i >> 5, jj = i & 31;
        W6f[t * 32 + jj] = make_float2(W6[jj * 64 + 2 * t], W6[jj * 64 + 2 * t + 1]);
    }
    int w = tid >> 5, j = tid & 31;
    if (w == 0) compute_eb64(b5, eb5, ebn25, j);
    if (w == 1) {
        float v0 = b6[j];
        float s2 = v0 * v0;
#pragma unroll
        for (int o = 16; o > 0; o >>= 1) s2 += __shfl_xor_sync(0xffffffffu, s2, o);
        float bn = sqrtf(s2), bc = fmaxf(bn, MINN);
        float se = __fdividef(fast_tanh(bc), bc);
        eb6[j] = v0 * se;
        if (j == 0) *ebn26 = (se * bn) * (se * bn);
    }
    __syncthreads();

    float2* xs = xall + w * 320;

    // ---- phase B: agg(g_t) + act + layer5(logmap) -> g_t2 ----
    for (int tile = blockIdx.x; tile < NODE_TILES; tile += gridDim.x) {
        int iBase = tile * 64 + w * 8;
        float t2[8], m0[8], m1[8], AA[8], BB[8];
        float c, ratio;
        agg_relu_stage(g_t, iBase, j, xs, t2);
        act_pre(t2, j, c, ratio);
        float2 ev = *(const float2*)(eb5 + 2 * j);
        fma_block64(Wf, xs, j, m0, m1);
        layer_post(m0, m1, c, ratio, ev, ebn25[0], true, AA, BB, j);
#pragma unroll
        for (int q = 0; q < 8; q++) {
            if (iBase + q < NN) {
                float v0 = AA[q] * m0[q] + BB[q] * ev.x;
                float v1 = AA[q] * m1[q] + BB[q] * ev.y;
                *((__half2*)g_t2 + (size_t)(iBase + q) * 32 + j) =
                    __floats2half2_rn(v0, v1);
            }
        }
    }

    grid_barrier();   // all g_t2 visible before any phase-C gather

    if (blockIdx.x == 0 && tid == 0) g_scan_done = 0;

    // ---- phase C: agg(g_t2) + act + layer6 -> out ----
    for (int tile = blockIdx.x; tile < NODE_TILES; tile += gridDim.x) {
        int iBase = tile * 64 + w * 8;
        float t2[8], AA[8], BB[8];
        float c, ratio;
        agg_relu_stage(g_t2, iBase, j, xs, t2);
        act_pre(t2, j, c, ratio);
        float e0 = eb6[j];
        float m[8];
        {
#pragma unroll
            for (int q = 0; q < 8; q++) m[q] = 0.f;
#pragma unroll
            for (int t = 0; t < 32; t++) {
                float2 wv = W6f[t * 32 + j];
                const float4* xt = (const float4*)(xs + t * 10);
                float4 xA = xt[0], xB = xt[1], xC = xt[2], xD = xt[3];
                m[0] = fmaf(xA.x, wv.x, fmaf(xA.y, wv.y, m[0]));
                m[1] = fmaf(xA.z, wv.x, fmaf(xA.w, wv.y, m[1]));
                m[2] = fmaf(xB.x, wv.x, fmaf(xB.y, wv.y, m[2]));
                m[3] = fmaf(xB.z, wv.x, fmaf(xB.w, wv.y, m[3]));
                m[4] = fmaf(xC.x, wv.x, fmaf(xC.y, wv.y, m[4]));
                m[5] = fmaf(xC.z, wv.x, fmaf(xC.w, wv.y, m[5]));
                m[6] = fmaf(xD.x, wv.x, fmaf(xD.y, wv.y, m[6]));
                m[7] = fmaf(xD.z, wv.x, fmaf(xD.w, wv.y, m[7]));
            }
        }
        {
            float s2[8], d[8];
#pragma unroll
            for (int q = 0; q < 8; q++) { s2[q] = m[q] * m[q]; d[q] = m[q] * e0; }
            float s2s, ds;
            rsum8x2(s2, d, j, s2s, ds);
            float ml = c * sqrtf(s2s);
            float mx = fmaxf(ml, MINN);
            float r = fast_tanh(mx * ratio);
            float sc = c * __fdividef(r, mx);
            float n1 = fmaxf(r * __fdividef(ml, mx), MINN);
            if (n1 > MAXN) { sc *= __fdividef(MAXN, n1); n1 = MAXN; }
            float xyv = sc * ds;
            float x2 = n1 * n1;
            float c1 = 1.f + 2.f * xyv + ebn26[0];
            float c2 = 1.f - x2;
            float iv = __fdividef(1.f, fmaxf(1.f + 2.f * xyv + x2 * ebn26[0], MINN));
            float q2v = iv * iv * (c1 * c1 * x2 + 2.f * c1 * c2 * xyv + c2 * c2 * ebn26[0]);
            float nf = fmaxf(sqrtf(q2v), MINN);
            float ps = 1.f;
            if (nf > MAXN) ps = __fdividef(MAXN, nf);
            float A = ps * iv * c1 * sc;
            float B = ps * iv * c2;
            bcast8(A, AA);
            bcast8(B, BB);
        }
#pragma unroll
        for (int q = 0; q < 8; q++)
            if (iBase + q < NN) out[(size_t)(iBase + q) * 32 + j] = AA[q] * m[q] + BB[q] * e0;

        // tail: zero g_cnt for the NEXT invocation
        int zb = tile * 64 + tid;
        if (tid < 64 && zb < NN) g_cnt[zb] = 0;
    }
}

// ---------------- CSR build ----------------
__global__ void __launch_bounds__(256) hist_kernel(const void* __restrict__ edges) {
    __shared__ int s_flag;
    int idx64 = local_idx64((const int*)edges, &s_flag);
    int i = blockIdx.x * 256 + threadIdx.x;   // over EE/2 pairs
    if (i >= EE / 2) return;
    int d0, d1;
    if (idx64) {
        longlong2 p = __ldg((const longlong2*)edges + EE / 2 + i);
        d0 = (int)p.x; d1 = (int)p.y;
    } else {
        int2 p = __ldg((const int2*)((const int*)edges + EE) + i);
        d0 = p.x; d1 = p.y;
    }
    atomicAdd(&g_cnt[d0], 1);
    atomicAdd(&g_cnt[d1], 1);
}

__global__ void __launch_bounds__(1024) scan_kernel() {
    __shared__ int sm[1024];
    __shared__ int base_s;
    int gi = blockIdx.x * 1024 + threadIdx.x;
    int v = (gi < NN) ? g_cnt[gi] : 0;
    sm[threadIdx.x] = v;
    __syncthreads();
#pragma unroll
    for (int o = 1; o < 1024; o <<= 1) {
        int t = (threadIdx.x >= o) ? sm[threadIdx.x - o] : 0;
        __syncthreads();
        sm[threadIdx.x] += t;
        __syncthreads();
    }
    int incl = sm[threadIdx.x];
    int excl = incl - v;
    if (threadIdx.x == 1023) {
        g_bsum[blockIdx.x] = incl;
        __threadfence();
        atomicAdd(&g_scan_done, 1);
    }
    if (threadIdx.x == 0) {
        while (*(volatile int*)&g_scan_done < SCAN_BLOCKS) {}
        __threadfence();
    }
    __syncthreads();
    if (threadIdx.x < 32) {
        int acc = 0;
        for (int i = (int)threadIdx.x; i < SCAN_BLOCKS; i += 32)
            if (i < (int)blockIdx.x) acc += g_bsum[i];
#pragma unroll
        for (int o = 16; o > 0; o >>= 1) acc += __shfl_xor_sync(0xffffffffu, acc, o);
        if (threadIdx.x == 0) base_s = acc;
    }
    __syncthreads();
    if (gi < NN) {
        int o = excl + base_s;
        g_off[gi] = o;
        g_cursor[gi] = o;
    }
    if (gi == 0) g_off[NN] = EE;
}

__global__ void __launch_bounds__(256) fill_kernel(const void* __restrict__ edges) {
    __shared__ int s_flag;
    int idx64 = local_idx64((const int*)edges, &s_flag);
    int i = blockIdx.x * 256 + threadIdx.x;   // over EE/2 pairs
    if (i >= EE / 2) return;
    int s0, s1, d0, d1;
    if (idx64) {
        longlong2 ps = __ldg((const longlong2*)edges + i);
        longlong2 pd = __ldg((const longlong2*)edges + EE / 2 + i);
        s0 = (int)ps.x; s1 = (int)ps.y;
        d0 = (int)pd.x; d1 = (int)pd.y;
    } else {
        int2 ps = __ldg((const int2*)edges + i);
        int2 pd = __ldg((const int2*)((const int*)edges + EE) + i);
        s0 = ps.x; s1 = ps.y;
        d0 = pd.x; d1 = pd.y;
    }
    g_col[atomicAdd(&g_cursor[d0], 1)] = s0;
    g_col[atomicAdd(&g_cursor[d1], 1)] = s1;
}

// ---------------- launch ----------------
extern "C" void kernel_launch(void* const* d_in, const int* in_sizes, int n_in,
                              void* d_out, int out_size) {
    const float* x = (const float*)d_in[0];
    const float* W1 = (const float*)d_in[1];
    const float* b1 = (const float*)d_in[2];
    const float* W2 = (const float*)d_in[3];
    const float* b2 = (const float*)d_in[4];
    const float* W3 = (const float*)d_in[5];
    const float* b3 = (const float*)d_in[6];
    const float* W4 = (const float*)d_in[7];
    const float* b4 = (const float*)d_in[8];
    const float* W5 = (const float*)d_in[9];
    const float* b5 = (const float*)d_in[10];
    const float* W6 = (const float*)d_in[11];
    const float* b6 = (const float*)d_in[12];
    const void* edges = d_in[13];
    float* out = (float*)d_out;

    const int SMEM_A = 4 * 1024 * 16 + 8 * 320 * 8 + 256 * 4 + 16;
    const int SMEM_BC = 1024 * 16 + 1024 * 8 + 8 * 320 * 8 + (64 + 1 + 32 + 1) * 4 + 16;

    cudaFuncSetAttribute(nodeA_kernel, cudaFuncAttributeMaxDynamicSharedMemorySize, SMEM_A);
    cudaFuncSetAttribute(nodeBC_kernel, cudaFuncAttributeMaxDynamicSharedMemorySize, SMEM_BC);

    const int PAIR_BLOCKS = (EE / 2 + 255) / 256;   // 3125

    cudaStream_t s2;
    cudaEvent_t ev0, evA;
    bool forked = (cudaStreamCreateWithFlags(&s2, cudaStreamNonBlocking) == cudaSuccess);
    if (forked) forked = (cudaEventCreateWithFlags(&ev0, cudaEventDisableTiming) == cudaSuccess);
    if (forked) forked = (cudaEventCreateWithFlags(&evA, cudaEventDisableTiming) == cudaSuccess);

    if (forked) {
        cudaEventRecord(ev0, 0);
        cudaStreamWaitEvent(s2, ev0, 0);
        nodeA_kernel<<<PERSIST_BLOCKS, 256, SMEM_A, s2>>>(x, W1, b1, W2, b2, W3, b3, W4, b4);
        cudaEventRecord(evA, s2);

        hist_kernel<<<PAIR_BLOCKS, 256>>>(edges);
        scan_kernel<<<SCAN_BLOCKS, 1024>>>();
        fill_kernel<<<PAIR_BLOCKS, 256>>>(edges);

        cudaStreamWaitEvent(0, evA, 0);
    } else {
        hist_kernel<<<PAIR_BLOCKS, 256>>>(edges);
        scan_kernel<<<SCAN_BLOCKS, 1024>>>();
        fill_kernel<<<PAIR_BLOCKS, 256>>>(edges);
        nodeA_kernel<<<PERSIST_BLOCKS, 256, SMEM_A>>>(x, W1, b1, W2, b2, W3, b3, W4, b4);
    }

    nodeBC_kernel<<<PERSIST_BLOCKS, 256, SMEM_BC>>>(W5, b5, W6, b6, out);
}

// round 16
// speedup vs baseline: 1.0485x; 1.0485x over previous
#include <cuda_runtime.h>
#include <cuda_fp16.h>
#include <cstdint>

#define NN 100000
#define EE 1600000
#define MINN 1e-15f
#define MAXN ((float)(1.0 - 1e-5))
#define SCAN_BLOCKS 98
#define NODE_TILES ((NN + 63) / 64)   // 64 nodes per tile (8 per warp)
#define PERSIST_BLOCKS 296            // 2 per SM on 148 SMs

// ---------------- scratch ----------------
__device__ __align__(16) __half g_t[(size_t)NN * 64];
__device__ __align__(16) __half g_t2[(size_t)NN * 64];
__device__ int g_col[EE];
__device__ int g_cnt[NN];          // zero at load; re-zeroed by nodeC tail
__device__ int g_off[NN + 1];
__device__ int g_cursor[NN];
__device__ int g_bsum[SCAN_BLOCKS];
__device__ int g_scan_done;        // zero at load; reset by nodeC
__device__ int g_ctrB;             // dynamic tile counter for nodeB (reset by nodeA)
__device__ int g_ctrC;             // dynamic tile counter for nodeC (reset by nodeB)

// ---------------- fast math (args nonnegative) ----------------
__device__ __forceinline__ float fast_tanh(float x) {
    float e = __expf(-2.f * x);
    return __fdividef(1.f - e, 1.f + e);
}
__device__ __forceinline__ float fast_atanh(float x) {
    x = fminf(x, MAXN);
    return 0.5f * __logf(__fdividef(1.f + x, 1.f - x));
}

// reduce v[8] across warp -> every lane gets total of slot (j&7). 9 SHFL.
__device__ __forceinline__ float rsum8(const float v[8], int j) {
    bool p1 = j & 1;
    float a[4];
#pragma unroll
    for (int i = 0; i < 4; i++) {
        float m = p1 ? v[2 * i + 1] : v[2 * i];
        float o = p1 ? v[2 * i] : v[2 * i + 1];
        a[i] = m + __shfl_xor_sync(0xffffffffu, o, 1);
    }
    bool p2 = j & 2;
    float b0, b1;
    {
        float m = p2 ? a[1] : a[0], o = p2 ? a[0] : a[1];
        b0 = m + __shfl_xor_sync(0xffffffffu, o, 2);
    }
    {
        float m = p2 ? a[3] : a[2], o = p2 ? a[2] : a[3];
        b1 = m + __shfl_xor_sync(0xffffffffu, o, 2);
    }
    bool p4 = j & 4;
    float m = p4 ? b1 : b0, o = p4 ? b0 : b1;
    float c = m + __shfl_xor_sync(0xffffffffu, o, 4);
    c += __shfl_xor_sync(0xffffffffu, c, 8);
    c += __shfl_xor_sync(0xffffffffu, c, 16);
    return c;
}

// two independent rsum8's interleaved (half the exposed shfl-chain depth)
__device__ __forceinline__ void rsum8x2(const float va[8], const float vb[8],
                                        int j, float& ra, float& rb) {
    bool p1 = j & 1;
    float A[4], B[4];
#pragma unroll
    for (int i = 0; i < 4; i++) {
        float am = p1 ? va[2 * i + 1] : va[2 * i];
        float ao = p1 ? va[2 * i] : va[2 * i + 1];
        float bm = p1 ? vb[2 * i + 1] : vb[2 * i];
        float bo = p1 ? vb[2 * i] : vb[2 * i + 1];
        A[i] = am + __shfl_xor_sync(0xffffffffu, ao, 1);
        B[i] = bm + __shfl_xor_sync(0xffffffffu, bo, 1);
    }
    bool p2 = j & 2;
    float a0, a1, b0, b1;
    { float m = p2 ? A[1] : A[0], o = p2 ? A[0] : A[1]; a0 = m + __shfl_xor_sync(0xffffffffu, o, 2); }
    { float m = p2 ? B[1] : B[0], o = p2 ? B[0] : B[1]; b0 = m + __shfl_xor_sync(0xffffffffu, o, 2); }
    { float m = p2 ? A[3] : A[2], o = p2 ? A[2] : A[3]; a1 = m + __shfl_xor_sync(0xffffffffu, o, 2); }
    { float m = p2 ? B[3] : B[2], o = p2 ? B[2] : B[3]; b1 = m + __shfl_xor_sync(0xffffffffu, o, 2); }
    bool p4 = j & 4;
    { float m = p4 ? a1 : a0, o = p4 ? a0 : a1; ra = m + __shfl_xor_sync(0xffffffffu, o, 4); }
    { float m = p4 ? b1 : b0, o = p4 ? b0 : b1; rb = m + __shfl_xor_sync(0xffffffffu, o, 4); }
    ra += __shfl_xor_sync(0xffffffffu, ra, 8);
    rb += __shfl_xor_sync(0xffffffffu, rb, 8);
    ra += __shfl_xor_sync(0xffffffffu, ra, 16);
    rb += __shfl_xor_sync(0xffffffffu, rb, 16);
}

__device__ __forceinline__ void bcast8(float v, float o[8]) {
#pragma unroll
    for (int q = 0; q < 8; q++) o[q] = __shfl_sync(0xffffffffu, v, q);
}

// stage 8 nodes: xs[j*10 + q] = float2(h0[q], h1[q]) (80B padded rows)
__device__ __forceinline__ void stage_x8(float2* xs, const float h0[8],
                                         const float h1[8], int j) {
    __syncwarp();
#pragma unroll
    for (int q = 0; q < 8; q++) xs[j * 10 + q] = make_float2(h0[q], h1[q]);
    __syncwarp();
}

// 64x64 matvec block: raw M for 8 nodes, plain scalar FFMA.
// Lane j owns output comps (2j,2j+1).
// Wf[t*32+j] = (W[2j][2t], W[2j][2t+1], W[2j+1][2t], W[2j+1][2t+1])
__device__ __forceinline__ void fma_block64(const float4* __restrict__ Wf,
                                            const float2* xs, int j,
                                            float m0[8], float m1[8]) {
#pragma unroll
    for (int q = 0; q < 8; q++) { m0[q] = 0.f; m1[q] = 0.f; }
#pragma unroll
    for (int t = 0; t < 32; t++) {
        float4 wv = Wf[t * 32 + j];
        const float4* xt = (const float4*)(xs + t * 10);
        float4 xA = xt[0], xB = xt[1], xC = xt[2], xD = xt[3];
        m0[0] = fmaf(xA.x, wv.x, fmaf(xA.y, wv.y, m0[0]));
        m1[0] = fmaf(xA.x, wv.z, fmaf(xA.y, wv.w, m1[0]));
        m0[1] = fmaf(xA.z, wv.x, fmaf(xA.w, wv.y, m0[1]));
        m1[1] = fmaf(xA.z, wv.z, fmaf(xA.w, wv.w, m1[1]));
        m0[2] = fmaf(xB.x, wv.x, fmaf(xB.y, wv.y, m0[2]));
        m1[2] = fmaf(xB.x, wv.z, fmaf(xB.y, wv.w, m1[2]));
        m0[3] = fmaf(xB.z, wv.x, fmaf(xB.w, wv.y, m0[3]));
        m1[3] = fmaf(xB.z, wv.z, fmaf(xB.w, wv.w, m1[3]));
        m0[4] = fmaf(xC.x, wv.x, fmaf(xC.y, wv.y, m0[4]));
        m1[4] = fmaf(xC.x, wv.z, fmaf(xC.y, wv.w, m1[4]));
        m0[5] = fmaf(xC.z, wv.x, fmaf(xC.w, wv.y, m0[5]));
        m1[5] = fmaf(xC.z, wv.z, fmaf(xC.w, wv.w, m1[5]));
        m0[6] = fmaf(xD.x, wv.x, fmaf(xD.y, wv.y, m0[6]));
        m1[6] = fmaf(xD.x, wv.z, fmaf(xD.y, wv.w, m1[6]));
        m0[7] = fmaf(xD.z, wv.x, fmaf(xD.w, wv.y, m0[7]));
        m1[7] = fmaf(xD.z, wv.z, fmaf(xD.w, wv.w, m1[7]));
    }
}

// post-matvec scalar chain -> broadcast coeffs AA,BB (out = AA*M + BB*e).
__device__ __forceinline__ void layer_post(
    const float m0[8], const float m1[8], float c, float ratio,
    float2 ev, float ebn2, bool with_sl, float AA[8], float BB[8], int j) {
    float s2[8], d[8];
#pragma unroll
    for (int q = 0; q < 8; q++) {
        s2[q] = m0[q] * m0[q] + m1[q] * m1[q];
        d[q] = m0[q] * ev.x + m1[q] * ev.y;
    }
    float s2s, ds;
    rsum8x2(s2, d, j, s2s, ds);
    float ml = c * sqrtf(s2s);
    float mx = fmaxf(ml, MINN);
    float r = fast_tanh(mx * ratio);
    float sc = c * __fdividef(r, mx);          // applies to raw M
    float n1 = fmaxf(r * __fdividef(ml, mx), MINN);
    if (n1 > MAXN) { sc *= __fdividef(MAXN, n1); n1 = MAXN; }
    float xyv = sc * ds;
    float x2 = n1 * n1;
    float c1 = 1.f + 2.f * xyv + ebn2;
    float c2 = 1.f - x2;
    float iv = __fdividef(1.f, fmaxf(1.f + 2.f * xyv + x2 * ebn2, MINN));
    float q2v = iv * iv * (c1 * c1 * x2 + 2.f * c1 * c2 * xyv + c2 * c2 * ebn2);
    float nf = fmaxf(sqrtf(q2v), MINN);
    float ps = 1.f;
    if (nf > MAXN) { ps = __fdividef(MAXN, nf); nf = MAXN; }
    float sl = with_sl ? __fdividef(fast_atanh(nf), nf) : 1.f;
    float A = ps * iv * c1 * sc * sl;
    float B = ps * iv * c2 * sl;
    bcast8(A, AA);
    bcast8(B, BB);
}

// act prelude for the NEXT layer from staged-u t2 partials.
__device__ __forceinline__ void act_pre(const float t2[8], int j,
                                        float& c, float& ratio) {
    float t2s = rsum8(t2, j);
    float tn = sqrtf(t2s);
    float tc = fmaxf(tn, MINN);
    float se = __fdividef(fast_tanh(tc), tc);
    float nn = fmaxf(se * tn, MINN);
    if (nn > MAXN) { se *= __fdividef(MAXN, nn); nn = MAXN; }
    c = se;
    ratio = __fdividef(fast_atanh(nn), nn);
}

// relu(A*M + B*e) -> unscaled u staged + t2 partials
__device__ __forceinline__ void relu_stage(const float m0[8], const float m1[8],
                                           const float AA[8], const float BB[8],
                                           float2 ev, float2* xs, int j, float t2[8]) {
#pragma unroll
    for (int q = 0; q < 8; q++) {
        float u0 = fmaxf(AA[q] * m0[q] + BB[q] * ev.x, 0.f);
        float u1 = fmaxf(AA[q] * m1[q] + BB[q] * ev.y, 0.f);
        t2[q] = u0 * u0 + u1 * u1;
        xs[j * 10 + q] = make_float2(u0, u1);
    }
    __syncwarp();
}

// bias -> eb = expmap0(b), |eb|^2, one warp
__device__ __forceinline__ void compute_eb64(const float* __restrict__ b,
                                             float* eb, float* ebn2, int j) {
    float v0 = b[j], v1 = b[32 + j];
    float s2 = v0 * v0 + v1 * v1;
#pragma unroll
    for (int o = 16; o > 0; o >>= 1) s2 += __shfl_xor_sync(0xffffffffu, s2, o);
    float bn = sqrtf(s2), bc = fmaxf(bn, MINN);
    float se = __fdividef(fast_tanh(bc), bc);
    eb[j] = v0 * se;
    eb[32 + j] = v1 * se;
    if (j == 0) *ebn2 = (se * bn) * (se * bn);
}

// CSR gather for one node; lane j sums comps (2j,2j+1) via half2 (4B/lane/nbr)
__device__ __forceinline__ void csr_agg(const __half* __restrict__ tsrc, int node,
                                        int j, float& o0, float& o1, int& deg) {
    const __half2* tp = (const __half2*)tsrc;
    int s = g_off[node], e = g_off[node + 1];
    deg = e - s;
    float a0 = 0.f, a1 = 0.f, b0 = 0.f, b1 = 0.f;
    for (int base = s; base < e; base += 32) {
        int nh = min(32, e - base);
        int idx = (j < nh) ? g_col[base + j] : 0;
        int t = 0;
        for (; t + 8 <= nh; t += 8) {
#pragma unroll
            for (int u = 0; u < 8; u += 2) {
                int sa = __shfl_sync(0xffffffffu, idx, t + u);
                int sb = __shfl_sync(0xffffffffu, idx, t + u + 1);
                float2 va = __half22float2(__ldg(tp + (size_t)sa * 32 + j));
                float2 vb = __half22float2(__ldg(tp + (size_t)sb * 32 + j));
                a0 += va.x; a1 += va.y;
                b0 += vb.x; b1 += vb.y;
            }
        }
        for (; t < nh; t++) {
            int sx = __shfl_sync(0xffffffffu, idx, t);
            float2 v = __half22float2(__ldg(tp + (size_t)sx * 32 + j));
            a0 += v.x; a1 += v.y;
        }
    }
    o0 = a0 + b0; o1 = a1 + b1;
}

// agg mean + (expmap0,proj,logmap0 folded) + relu -> unscaled u staged + t2
__device__ __forceinline__ void agg_relu_stage(const __half* __restrict__ tsrc,
                                               int iBase, int j, float2* xs,
                                               float t2[8]) {
    float h0[8], h1[8], n2[8];
#pragma unroll
    for (int q = 0; q < 8; q++) {
        int node = min(iBase + q, NN - 1);
        int deg;
        float a0, a1;
        csr_agg(tsrc, node, j, a0, a1, deg);
        float inv = __fdividef(1.f, fmaxf((float)deg, 1.f));
        h0[q] = a0 * inv;
        h1[q] = a1 * inv;
        n2[q] = h0[q] * h0[q] + h1[q] * h1[q];
    }
    float n2s = rsum8(n2, j);
    float un = sqrtf(n2s);
    float uc = fmaxf(un, MINN);
    float se = __fdividef(fast_tanh(uc), uc);
    float nn = fmaxf(se * un, MINN);
    if (nn > MAXN) { se *= __fdividef(MAXN, nn); nn = MAXN; }
    float comb = se * __fdividef(fast_atanh(nn), nn);
    float CB[8];
    bcast8(comb, CB);
#pragma unroll
    for (int q = 0; q < 8; q++) {
        float u0 = fmaxf(h0[q] * CB[q], 0.f);
        float u1 = fmaxf(h1[q] * CB[q], 0.f);
        t2[q] = u0 * u0 + u1 * u1;
        xs[j * 10 + q] = make_float2(u0, u1);
    }
    __syncwarp();
}

// load weights: Wf[t*32+j] = (W[2j][2t], W[2j][2t+1], W[2j+1][2t], W[2j+1][2t+1])
__device__ __forceinline__ void load_Wq(float4* Wf, const float* __restrict__ W,
                                        int K, int tid) {
    for (int i = tid; i < 1024; i += 256) {
        int t = i >> 5, jj = i & 31;
        int k0 = 2 * t, k1 = 2 * t + 1;
        int r0 = 2 * jj, r1 = 2 * jj + 1;
        float4 v;
        v.x = W[r0 * K + k0];
        v.y = (k1 < K) ? W[r0 * K + k1] : 0.f;
        v.z = W[r1 * K + k0];
        v.w = (k1 < K) ? W[r1 * K + k1] : 0.f;
        Wf[t * 32 + jj] = v;
    }
}

// block-local edge dtype detection
__device__ __forceinline__ int local_idx64(const int* __restrict__ e32, int* s_flag) {
    if (threadIdx.x == 0) *s_flag = 1;
    __syncthreads();
    if (threadIdx.x < 256 && e32[2 * threadIdx.x + 1] != 0) *s_flag = 0;
    __syncthreads();
    return *s_flag;
}

// ---------------- kernel A: poincare + layers 1..4 + logmap -> g_t ----------
__global__ void __launch_bounds__(256, 2) nodeA_kernel(
    const float* __restrict__ x,
    const float* __restrict__ W1, const float* __restrict__ b1,
    const float* __restrict__ W2, const float* __restrict__ b2,
    const float* __restrict__ W3, const float* __restrict__ b3,
    const float* __restrict__ W4, const float* __restrict__ b4) {
    extern __shared__ unsigned char smem_raw[];
    float4* Wf = (float4*)smem_raw;              // 4*1024 float4 = 64KB
    float2* xall = (float2*)(Wf + 4 * 1024);     // 8 warps * 320 float2 = 20KB
    float* eb = (float*)(xall + 8 * 320);
    float* ebn2 = eb + 256;
    int tid = threadIdx.x;

    if (blockIdx.x == 0 && tid == 0) g_ctrB = 0;   // counter for nodeB

    load_Wq(Wf,        W1, 63, tid);
    load_Wq(Wf + 1024, W2, 64, tid);
    load_Wq(Wf + 2048, W3, 64, tid);
    load_Wq(Wf + 3072, W4, 64, tid);
    int w = tid >> 5, j = tid & 31;
    if (w < 4) {
        const float* bp[4] = {b1, b2, b3, b4};
        compute_eb64(bp[w], eb + w * 64, ebn2 + w, j);
    }
    __syncthreads();

    float2* xs = xall + w * 320;

    for (int tile = blockIdx.x; tile < NODE_TILES; tile += gridDim.x) {
        int iBase = tile * 64 + w * 8;
        float t2[8], m0[8], m1[8], AA[8], BB[8];
        float c, ratio;

        // poincare map (raw; proj scale deferred into c)
        {
            float h0[8], h1[8], n2[8];
#pragma unroll
            for (int q = 0; q < 8; q++) {
                const float* xp = x + (size_t)min(iBase + q, NN - 1) * 64;
                float inv = __fdividef(1.f, xp[0] + 1.f);
                h0[q] = xp[1 + 2 * j] * inv;
                h1[q] = (j < 31) ? xp[2 + 2 * j] * inv : 0.f;
                n2[q] = h0[q] * h0[q] + h1[q] * h1[q];
            }
            stage_x8(xs, h0, h1, j);
            float n2s = rsum8(n2, j);
            float nf = fmaxf(sqrtf(n2s), MINN);
            float ps = 1.f;
            if (nf > MAXN) { ps = __fdividef(MAXN, nf); nf = MAXN; }
            c = ps;
            ratio = __fdividef(fast_atanh(nf), nf);
        }

        float2 ev;
        ev = *(const float2*)(eb + 2 * j);
        fma_block64(Wf, xs, j, m0, m1);
        layer_post(m0, m1, c, ratio, ev, ebn2[0], true, AA, BB, j);
        relu_stage(m0, m1, AA, BB, ev, xs, j, t2);
        act_pre(t2, j, c, ratio);

        ev = *(const float2*)(eb + 64 + 2 * j);
        fma_block64(Wf + 1024, xs, j, m0, m1);
        layer_post(m0, m1, c, ratio, ev, ebn2[1], true, AA, BB, j);
        relu_stage(m0, m1, AA, BB, ev, xs, j, t2);
        act_pre(t2, j, c, ratio);

        ev = *(const float2*)(eb + 128 + 2 * j);
        fma_block64(Wf + 2048, xs, j, m0, m1);
        layer_post(m0, m1, c, ratio, ev, ebn2[2], true, AA, BB, j);
        relu_stage(m0, m1, AA, BB, ev, xs, j, t2);
        act_pre(t2, j, c, ratio);

        ev = *(const float2*)(eb + 192 + 2 * j);
        fma_block64(Wf + 3072, xs, j, m0, m1);
        layer_post(m0, m1, c, ratio, ev, ebn2[3], true, AA, BB, j);
#pragma unroll
        for (int q = 0; q < 8; q++) {
            if (iBase + q < NN) {
                float v0 = AA[q] * m0[q] + BB[q] * ev.x;
                float v1 = AA[q] * m1[q] + BB[q] * ev.y;
                *((__half2*)g_t + (size_t)(iBase + q) * 32 + j) =
                    __floats2half2_rn(v0, v1);
            }
        }
    }
}

// ---------------- kernel B: agg(g_t)+act + layer5(logmap) -> g_t2 -----------
__global__ void __launch_bounds__(256, 2) nodeB_kernel(
    const float* __restrict__ W5, const float* __restrict__ b5) {
    extern __shared__ unsigned char smem_raw[];
    float4* Wf = (float4*)smem_raw;              // 1024 float4 = 16KB
    float2* xall = (float2*)(Wf + 1024);
    float* eb = (float*)(xall + 8 * 320);
    float* ebn2 = eb + 64;
    __shared__ int s_tile;
    int tid = threadIdx.x;

    if (blockIdx.x == 0 && tid == 0) g_ctrC = 0;   // counter for nodeC

    load_Wq(Wf, W5, 64, tid);
    int w = tid >> 5, j = tid & 31;
    if (w == 0) compute_eb64(b5, eb, ebn2, j);
    __syncthreads();

    float2* xs = xall + w * 320;

    for (;;) {
        __syncthreads();
        if (tid == 0) s_tile = atomicAdd(&g_ctrB, 1);
        __syncthreads();
        int tile = s_tile;
        if (tile >= NODE_TILES) break;
        int iBase = tile * 64 + w * 8;
        float t2[8], m0[8], m1[8], AA[8], BB[8];
        float c, ratio;
        agg_relu_stage(g_t, iBase, j, xs, t2);
        act_pre(t2, j, c, ratio);
        float2 ev = *(const float2*)(eb + 2 * j);
        fma_block64(Wf, xs, j, m0, m1);
        layer_post(m0, m1, c, ratio, ev, ebn2[0], true, AA, BB, j);
#pragma unroll
        for (int q = 0; q < 8; q++) {
            if (iBase + q < NN) {
                float v0 = AA[q] * m0[q] + BB[q] * ev.x;
                float v1 = AA[q] * m1[q] + BB[q] * ev.y;
                *((__half2*)g_t2 + (size_t)(iBase + q) * 32 + j) =
                    __floats2half2_rn(v0, v1);
            }
        }
    }
    // PDL: signal dependents (nodeC) that our g_t2 writes are done
    asm volatile("griddepcontrol.launch_dependents;");
}

// ---------------- kernel C: agg(g_t2)+act + layer6 -> out -------------------
__global__ void __launch_bounds__(256, 2) nodeC_kernel(
    const float* __restrict__ W6, const float* __restrict__ b6,
    float* __restrict__ out) {
    extern __shared__ unsigned char smem_raw[];
    float2* W6f = (float2*)smem_raw;             // 1024 float2 = 8KB
    float2* xall = W6f + 1024;
    float* eb = (float*)(xall + 8 * 320);
    float* ebn2 = eb + 32;
    __shared__ int s_tile;
    int tid = threadIdx.x;
    for (int i = tid; i < 1024; i += 256) {
        int t = i >> 5, jj = i & 31;
        W6f[t * 32 + jj] = make_float2(W6[jj * 64 + 2 * t], W6[jj * 64 + 2 * t + 1]);
    }
    int w = tid >> 5, j = tid & 31;
    if (w == 0) {
        float v0 = b6[j];
        float s2 = v0 * v0;
#pragma unroll
        for (int o = 16; o > 0; o >>= 1) s2 += __shfl_xor_sync(0xffffffffu, s2, o);
        float bn = sqrtf(s2), bc = fmaxf(bn, MINN);
        float se = __fdividef(fast_tanh(bc), bc);
        eb[j] = v0 * se;
        if (j == 0) *ebn2 = (se * bn) * (se * bn);
    }
    __syncthreads();
    // PDL: prologue above is independent of nodeB; wait before touching g_t2
    asm volatile("griddepcontrol.wait;" ::: "memory");

    float2* xs = xall + w * 320;
    if (blockIdx.x == 0 && tid == 0) g_scan_done = 0;

    for (;;) {
        __syncthreads();
        if (tid == 0) s_tile = atomicAdd(&g_ctrC, 1);
        __syncthreads();
        int tile = s_tile;
        if (tile >= NODE_TILES) break;
        int iBase = tile * 64 + w * 8;
        float t2[8], AA[8], BB[8];
        float c, ratio;
        agg_relu_stage(g_t2, iBase, j, xs, t2);
        act_pre(t2, j, c, ratio);
        float e0 = eb[j];
        float m[8];
        {
#pragma unroll
            for (int q = 0; q < 8; q++) m[q] = 0.f;
#pragma unroll
            for (int t = 0; t < 32; t++) {
                float2 wv = W6f[t * 32 + j];
                const float4* xt = (const float4*)(xs + t * 10);
                float4 xA = xt[0], xB = xt[1], xC = xt[2], xD = xt[3];
                m[0] = fmaf(xA.x, wv.x, fmaf(xA.y, wv.y, m[0]));
                m[1] = fmaf(xA.z, wv.x, fmaf(xA.w, wv.y, m[1]));
                m[2] = fmaf(xB.x, wv.x, fmaf(xB.y, wv.y, m[2]));
                m[3] = fmaf(xB.z, wv.x, fmaf(xB.w, wv.y, m[3]));
                m[4] = fmaf(xC.x, wv.x, fmaf(xC.y, wv.y, m[4]));
                m[5] = fmaf(xC.z, wv.x, fmaf(xC.w, wv.y, m[5]));
                m[6] = fmaf(xD.x, wv.x, fmaf(xD.y, wv.y, m[6]));
                m[7] = fmaf(xD.z, wv.x, fmaf(xD.w, wv.y, m[7]));
            }
        }
        {
            float s2[8], d[8];
#pragma unroll
            for (int q = 0; q < 8; q++) { s2[q] = m[q] * m[q]; d[q] = m[q] * e0; }
            float s2s, ds;
            rsum8x2(s2, d, j, s2s, ds);
            float ml = c * sqrtf(s2s);
            float mx = fmaxf(ml, MINN);
            float r = fast_tanh(mx * ratio);
            float sc = c * __fdividef(r, mx);
            float n1 = fmaxf(r * __fdividef(ml, mx), MINN);
            if (n1 > MAXN) { sc *= __fdividef(MAXN, n1); n1 = MAXN; }
            float xyv = sc * ds;
            float x2 = n1 * n1;
            float c1 = 1.f + 2.f * xyv + ebn2[0];
            float c2 = 1.f - x2;
            float iv = __fdividef(1.f, fmaxf(1.f + 2.f * xyv + x2 * ebn2[0], MINN));
            float q2v = iv * iv * (c1 * c1 * x2 + 2.f * c1 * c2 * xyv + c2 * c2 * ebn2[0]);
            float nf = fmaxf(sqrtf(q2v), MINN);
            float ps = 1.f;
            if (nf > MAXN) ps = __fdividef(MAXN, nf);
            float A = ps * iv * c1 * sc;
            float B = ps * iv * c2;
            bcast8(A, AA);
            bcast8(B, BB);
        }
#pragma unroll
        for (int q = 0; q < 8; q++)
            if (iBase + q < NN) out[(size_t)(iBase + q) * 32 + j] = AA[q] * m[q] + BB[q] * e0;

        // tail: zero g_cnt for the NEXT invocation (tiles cover all NN once)
        int zb = tile * 64 + tid;
        if (tid < 64 && zb < NN) g_cnt[zb] = 0;
    }
}

// ---------------- CSR build ----------------
__global__ void __launch_bounds__(256) hist_kernel(const void* __restrict__ edges) {
    __shared__ int s_flag;
    int idx64 = local_idx64((const int*)edges, &s_flag);
    int i = blockIdx.x * 256 + threadIdx.x;   // over EE/2 pairs
    if (i >= EE / 2) return;
    int d0, d1;
    if (idx64) {
        longlong2 p = __ldg((const longlong2*)edges + EE / 2 + i);
        d0 = (int)p.x; d1 = (int)p.y;
    } else {
        int2 p = __ldg((const int2*)((const int*)edges + EE) + i);
        d0 = p.x; d1 = p.y;
    }
    atomicAdd(&g_cnt[d0], 1);
    atomicAdd(&g_cnt[d1], 1);
}

__global__ void __launch_bounds__(1024) scan_kernel() {
    __shared__ int sm[1024];
    __shared__ int base_s;
    int gi = blockIdx.x * 1024 + threadIdx.x;
    int v = (gi < NN) ? g_cnt[gi] : 0;
    sm[threadIdx.x] = v;
    __syncthreads();
#pragma unroll
    for (int o = 1; o < 1024; o <<= 1) {
        int t = (threadIdx.x >= o) ? sm[threadIdx.x - o] : 0;
        __syncthreads();
        sm[threadIdx.x] += t;
        __syncthreads();
    }
    int incl = sm[threadIdx.x];
    int excl = incl - v;
    if (threadIdx.x == 1023) {
        g_bsum[blockIdx.x] = incl;
        __threadfence();
        atomicAdd(&g_scan_done, 1);
    }
    if (threadIdx.x == 0) {
        while (*(volatile int*)&g_scan_done < SCAN_BLOCKS) {}
        __threadfence();
    }
    __syncthreads();
    if (threadIdx.x < 32) {
        int acc = 0;
        for (int i = (int)threadIdx.x; i < SCAN_BLOCKS; i += 32)
            if (i < (int)blockIdx.x) acc += g_bsum[i];
#pragma unroll
        for (int o = 16; o > 0; o >>= 1) acc += __shfl_xor_sync(0xffffffffu, acc, o);
        if (threadIdx.x == 0) base_s = acc;
    }
    __syncthreads();
    if (gi < NN) {
        int o = excl + base_s;
        g_off[gi] = o;
        g_cursor[gi] = o;
    }
    if (gi == 0) g_off[NN] = EE;
}

__global__ void __launch_bounds__(256) fill_kernel(const void* __restrict__ edges) {
    __shared__ int s_flag;
    int idx64 = local_idx64((const int*)edges, &s_flag);
    int i = blockIdx.x * 256 + threadIdx.x;   // over EE/2 pairs
    if (i >= EE / 2) return;
    int s0, s1, d0, d1;
    if (idx64) {
        longlong2 ps = __ldg((const longlong2*)edges + i);
        longlong2 pd = __ldg((const longlong2*)edges + EE / 2 + i);
        s0 = (int)ps.x; s1 = (int)ps.y;
        d0 = (int)pd.x; d1 = (int)pd.y;
    } else {
        int2 ps = __ldg((const int2*)edges + i);
        int2 pd = __ldg((const int2*)((const int*)edges + EE) + i);
        s0 = ps.x; s1 = ps.y;
        d0 = pd.x; d1 = pd.y;
    }
    g_col[atomicAdd(&g_cursor[d0], 1)] = s0;
    g_col[atomicAdd(&g_cursor[d1], 1)] = s1;
}

// ---------------- launch ----------------
extern "C" void kernel_launch(void* const* d_in, const int* in_sizes, int n_in,
                              void* d_out, int out_size) {
    const float* x = (const float*)d_in[0];
    const float* W1 = (const float*)d_in[1];
    const float* b1 = (const float*)d_in[2];
    const float* W2 = (const float*)d_in[3];
    const float* b2 = (const float*)d_in[4];
    const float* W3 = (const float*)d_in[5];
    const float* b3 = (const float*)d_in[6];
    const float* W4 = (const float*)d_in[7];
    const float* b4 = (const float*)d_in[8];
    const float* W5 = (const float*)d_in[9];
    const float* b5 = (const float*)d_in[10];
    const float* W6 = (const float*)d_in[11];
    const float* b6 = (const float*)d_in[12];
    const void* edges = d_in[13];
    float* out = (float*)d_out;

    const int SMEM_A = 4 * 1024 * 16 + 8 * 320 * 8 + 256 * 4 + 16;
    const int SMEM_B = 1024 * 16 + 8 * 320 * 8 + 64 * 4 + 16;
    const int SMEM_C = 1024 * 8 + 8 * 320 * 8 + 32 * 4 + 16;

    cudaFuncSetAttribute(nodeA_kernel, cudaFuncAttributeMaxDynamicSharedMemorySize, SMEM_A);
    cudaFuncSetAttribute(nodeB_kernel, cudaFuncAttributeMaxDynamicSharedMemorySize, SMEM_B);
    cudaFuncSetAttribute(nodeC_kernel, cudaFuncAttributeMaxDynamicSharedMemorySize, SMEM_C);

    const int PAIR_BLOCKS = (EE / 2 + 255) / 256;   // 3125

    cudaStream_t s2;
    cudaEvent_t ev0, evA;
    bool forked = (cudaStreamCreateWithFlags(&s2, cudaStreamNonBlocking) == cudaSuccess);
    if (forked) forked = (cudaEventCreateWithFlags(&ev0, cudaEventDisableTiming) == cudaSuccess);
    if (forked) forked = (cudaEventCreateWithFlags(&evA, cudaEventDisableTiming) == cudaSuccess);

    if (forked) {
        cudaEventRecord(ev0, 0);
        cudaStreamWaitEvent(s2, ev0, 0);
        nodeA_kernel<<<PERSIST_BLOCKS, 256, SMEM_A, s2>>>(x, W1, b1, W2, b2, W3, b3, W4, b4);
        cudaEventRecord(evA, s2);

        hist_kernel<<<PAIR_BLOCKS, 256>>>(edges);
        scan_kernel<<<SCAN_BLOCKS, 1024>>>();
        fill_kernel<<<PAIR_BLOCKS, 256>>>(edges);

        cudaStreamWaitEvent(0, evA, 0);
    } else {
        hist_kernel<<<PAIR_BLOCKS, 256>>>(edges);
        scan_kernel<<<SCAN_BLOCKS, 1024>>>();
        fill_kernel<<<PAIR_BLOCKS, 256>>>(edges);
        nodeA_kernel<<<PERSIST_BLOCKS, 256, SMEM_A>>>(x, W1, b1, W2, b2, W3, b3, W4, b4);
    }

    nodeB_kernel<<<PERSIST_BLOCKS, 256, SMEM_B>>>(W5, b5);

    // nodeC with programmatic dependent launch (prologue overlaps nodeB tail);
    // falls back to a plain launch if the attribute isn't accepted.
    {
        cudaLaunchConfig_t cfg = {};
        cfg.gridDim = dim3(PERSIST_BLOCKS);
        cfg.blockDim = dim3(256);
        cfg.dynamicSmemBytes = SMEM_C;
        cfg.stream = 0;
        cudaLaunchAttribute at[1];
        at[0].id = cudaLaunchAttributeProgrammaticStreamSerialization;
        at[0].val.programmaticStreamSerializationAllowed = 1;
        cfg.attrs = at;
        cfg.numAttrs = 1;
        if (cudaLaunchKernelEx(&cfg, nodeC_kernel, W6, b6, out) != cudaSuccess)
            nodeC_kernel<<<PERSIST_BLOCKS, 256, SMEM_C>>>(W6, b6, out);
    }
}

// round 17
// speedup vs baseline: 1.1286x; 1.0764x over previous
#include <cuda_runtime.h>
#include <cuda_fp16.h>
#include <cstdint>

#define NN 100000
#define EE 1600000
#define MINN 1e-15f
#define MAXN ((float)(1.0 - 1e-5))
#define SCAN_BLOCKS 98
#define NODE_TILES ((NN + 63) / 64)   // 64 nodes per tile (nodeA: 8 per warp)
#define NCHUNK ((NN + 7) / 8)         // 8-node warp chunks for nodeB/C
#define PERSIST_BLOCKS 296            // 2 per SM on 148 SMs

// ---------------- scratch ----------------
__device__ __align__(16) __half g_t[(size_t)NN * 64];
__device__ __align__(16) __half g_t2[(size_t)NN * 64];
__device__ int g_col[EE];
__device__ int g_cnt[NN];          // zero at load; re-zeroed by nodeC tail
__device__ int g_off[NN + 1];
__device__ int g_cursor[NN];
__device__ int g_bsum[SCAN_BLOCKS];
__device__ int g_scan_done;        // zero at load; reset by nodeC
__device__ int g_ctrB;             // warp-chunk counter for nodeB (reset by nodeA)
__device__ int g_ctrC;             // warp-chunk counter for nodeC (reset by nodeB)

// ---------------- fast math (args nonnegative) ----------------
__device__ __forceinline__ float fast_tanh(float x) {
    float e = __expf(-2.f * x);
    return __fdividef(1.f - e, 1.f + e);
}
__device__ __forceinline__ float fast_atanh(float x) {
    x = fminf(x, MAXN);
    return 0.5f * __logf(__fdividef(1.f + x, 1.f - x));
}

// reduce v[8] across warp -> every lane gets total of slot (j&7). 9 SHFL.
__device__ __forceinline__ float rsum8(const float v[8], int j) {
    bool p1 = j & 1;
    float a[4];
#pragma unroll
    for (int i = 0; i < 4; i++) {
        float m = p1 ? v[2 * i + 1] : v[2 * i];
        float o = p1 ? v[2 * i] : v[2 * i + 1];
        a[i] = m + __shfl_xor_sync(0xffffffffu, o, 1);
    }
    bool p2 = j & 2;
    float b0, b1;
    {
        float m = p2 ? a[1] : a[0], o = p2 ? a[0] : a[1];
        b0 = m + __shfl_xor_sync(0xffffffffu, o, 2);
    }
    {
        float m = p2 ? a[3] : a[2], o = p2 ? a[2] : a[3];
        b1 = m + __shfl_xor_sync(0xffffffffu, o, 2);
    }
    bool p4 = j & 4;
    float m = p4 ? b1 : b0, o = p4 ? b0 : b1;
    float c = m + __shfl_xor_sync(0xffffffffu, o, 4);
    c += __shfl_xor_sync(0xffffffffu, c, 8);
    c += __shfl_xor_sync(0xffffffffu, c, 16);
    return c;
}

// two independent rsum8's interleaved (half the exposed shfl-chain depth)
__device__ __forceinline__ void rsum8x2(const float va[8], const float vb[8],
                                        int j, float& ra, float& rb) {
    bool p1 = j & 1;
    float A[4], B[4];
#pragma unroll
    for (int i = 0; i < 4; i++) {
        float am = p1 ? va[2 * i + 1] : va[2 * i];
        float ao = p1 ? va[2 * i] : va[2 * i + 1];
        float bm = p1 ? vb[2 * i + 1] : vb[2 * i];
        float bo = p1 ? vb[2 * i] : vb[2 * i + 1];
        A[i] = am + __shfl_xor_sync(0xffffffffu, ao, 1);
        B[i] = bm + __shfl_xor_sync(0xffffffffu, bo, 1);
    }
    bool p2 = j & 2;
    float a0, a1, b0, b1;
    { float m = p2 ? A[1] : A[0], o = p2 ? A[0] : A[1]; a0 = m + __shfl_xor_sync(0xffffffffu, o, 2); }
    { float m = p2 ? B[1] : B[0], o = p2 ? B[0] : B[1]; b0 = m + __shfl_xor_sync(0xffffffffu, o, 2); }
    { float m = p2 ? A[3] : A[2], o = p2 ? A[2] : A[3]; a1 = m + __shfl_xor_sync(0xffffffffu, o, 2); }
    { float m = p2 ? B[3] : B[2], o = p2 ? B[2] : B[3]; b1 = m + __shfl_xor_sync(0xffffffffu, o, 2); }
    bool p4 = j & 4;
    { float m = p4 ? a1 : a0, o = p4 ? a0 : a1; ra = m + __shfl_xor_sync(0xffffffffu, o, 4); }
    { float m = p4 ? b1 : b0, o = p4 ? b0 : b1; rb = m + __shfl_xor_sync(0xffffffffu, o, 4); }
    ra += __shfl_xor_sync(0xffffffffu, ra, 8);
    rb += __shfl_xor_sync(0xffffffffu, rb, 8);
    ra += __shfl_xor_sync(0xffffffffu, ra, 16);
    rb += __shfl_xor_sync(0xffffffffu, rb, 16);
}

__device__ __forceinline__ void bcast8(float v, float o[8]) {
#pragma unroll
    for (int q = 0; q < 8; q++) o[q] = __shfl_sync(0xffffffffu, v, q);
}

// stage 8 nodes: xs[j*10 + q] = float2(h0[q], h1[q]) (80B padded rows)
__device__ __forceinline__ void stage_x8(float2* xs, const float h0[8],
                                         const float h1[8], int j) {
    __syncwarp();
#pragma unroll
    for (int q = 0; q < 8; q++) xs[j * 10 + q] = make_float2(h0[q], h1[q]);
    __syncwarp();
}

// 64x64 matvec block: raw M for 8 nodes, plain scalar FFMA.
// Lane j owns output comps (2j,2j+1).
// Wf[t*32+j] = (W[2j][2t], W[2j][2t+1], W[2j+1][2t], W[2j+1][2t+1])
__device__ __forceinline__ void fma_block64(const float4* __restrict__ Wf,
                                            const float2* xs, int j,
                                            float m0[8], float m1[8]) {
#pragma unroll
    for (int q = 0; q < 8; q++) { m0[q] = 0.f; m1[q] = 0.f; }
#pragma unroll
    for (int t = 0; t < 32; t++) {
        float4 wv = Wf[t * 32 + j];
        const float4* xt = (const float4*)(xs + t * 10);
        float4 xA = xt[0], xB = xt[1], xC = xt[2], xD = xt[3];
        m0[0] = fmaf(xA.x, wv.x, fmaf(xA.y, wv.y, m0[0]));
        m1[0] = fmaf(xA.x, wv.z, fmaf(xA.y, wv.w, m1[0]));
        m0[1] = fmaf(xA.z, wv.x, fmaf(xA.w, wv.y, m0[1]));
        m1[1] = fmaf(xA.z, wv.z, fmaf(xA.w, wv.w, m1[1]));
        m0[2] = fmaf(xB.x, wv.x, fmaf(xB.y, wv.y, m0[2]));
        m1[2] = fmaf(xB.x, wv.z, fmaf(xB.y, wv.w, m1[2]));
        m0[3] = fmaf(xB.z, wv.x, fmaf(xB.w, wv.y, m0[3]));
        m1[3] = fmaf(xB.z, wv.z, fmaf(xB.w, wv.w, m1[3]));
        m0[4] = fmaf(xC.x, wv.x, fmaf(xC.y, wv.y, m0[4]));
        m1[4] = fmaf(xC.x, wv.z, fmaf(xC.y, wv.w, m1[4]));
        m0[5] = fmaf(xC.z, wv.x, fmaf(xC.w, wv.y, m0[5]));
        m1[5] = fmaf(xC.z, wv.z, fmaf(xC.w, wv.w, m1[5]));
        m0[6] = fmaf(xD.x, wv.x, fmaf(xD.y, wv.y, m0[6]));
        m1[6] = fmaf(xD.x, wv.z, fmaf(xD.y, wv.w, m1[6]));
        m0[7] = fmaf(xD.z, wv.x, fmaf(xD.w, wv.y, m0[7]));
        m1[7] = fmaf(xD.z, wv.z, fmaf(xD.w, wv.w, m1[7]));
    }
}

// post-matvec scalar chain -> broadcast coeffs AA,BB (out = AA*M + BB*e).
__device__ __forceinline__ void layer_post(
    const float m0[8], const float m1[8], float c, float ratio,
    float2 ev, float ebn2, bool with_sl, float AA[8], float BB[8], int j) {
    float s2[8], d[8];
#pragma unroll
    for (int q = 0; q < 8; q++) {
        s2[q] = m0[q] * m0[q] + m1[q] * m1[q];
        d[q] = m0[q] * ev.x + m1[q] * ev.y;
    }
    float s2s, ds;
    rsum8x2(s2, d, j, s2s, ds);
    float ml = c * sqrtf(s2s);
    float mx = fmaxf(ml, MINN);
    float r = fast_tanh(mx * ratio);
    float sc = c * __fdividef(r, mx);          // applies to raw M
    float n1 = fmaxf(r * __fdividef(ml, mx), MINN);
    if (n1 > MAXN) { sc *= __fdividef(MAXN, n1); n1 = MAXN; }
    float xyv = sc * ds;
    float x2 = n1 * n1;
    float c1 = 1.f + 2.f * xyv + ebn2;
    float c2 = 1.f - x2;
    float iv = __fdividef(1.f, fmaxf(1.f + 2.f * xyv + x2 * ebn2, MINN));
    float q2v = iv * iv * (c1 * c1 * x2 + 2.f * c1 * c2 * xyv + c2 * c2 * ebn2);
    float nf = fmaxf(sqrtf(q2v), MINN);
    float ps = 1.f;
    if (nf > MAXN) { ps = __fdividef(MAXN, nf); nf = MAXN; }
    float sl = with_sl ? __fdividef(fast_atanh(nf), nf) : 1.f;
    float A = ps * iv * c1 * sc * sl;
    float B = ps * iv * c2 * sl;
    bcast8(A, AA);
    bcast8(B, BB);
}

// act prelude for the NEXT layer from staged-u t2 partials.
__device__ __forceinline__ void act_pre(const float t2[8], int j,
                                        float& c, float& ratio) {
    float t2s = rsum8(t2, j);
    float tn = sqrtf(t2s);
    float tc = fmaxf(tn, MINN);
    float se = __fdividef(fast_tanh(tc), tc);
    float nn = fmaxf(se * tn, MINN);
    if (nn > MAXN) { se *= __fdividef(MAXN, nn); nn = MAXN; }
    c = se;
    ratio = __fdividef(fast_atanh(nn), nn);
}

// relu(A*M + B*e) -> unscaled u staged + t2 partials
__device__ __forceinline__ void relu_stage(const float m0[8], const float m1[8],
                                           const float AA[8], const float BB[8],
                                           float2 ev, float2* xs, int j, float t2[8]) {
#pragma unroll
    for (int q = 0; q < 8; q++) {
        float u0 = fmaxf(AA[q] * m0[q] + BB[q] * ev.x, 0.f);
        float u1 = fmaxf(AA[q] * m1[q] + BB[q] * ev.y, 0.f);
        t2[q] = u0 * u0 + u1 * u1;
        xs[j * 10 + q] = make_float2(u0, u1);
    }
    __syncwarp();
}

// bias -> eb = expmap0(b), |eb|^2, one warp
__device__ __forceinline__ void compute_eb64(const float* __restrict__ b,
                                             float* eb, float* ebn2, int j) {
    float v0 = b[j], v1 = b[32 + j];
    float s2 = v0 * v0 + v1 * v1;
#pragma unroll
    for (int o = 16; o > 0; o >>= 1) s2 += __shfl_xor_sync(0xffffffffu, s2, o);
    float bn = sqrtf(s2), bc = fmaxf(bn, MINN);
    float se = __fdividef(fast_tanh(bc), bc);
    eb[j] = v0 * se;
    eb[32 + j] = v1 * se;
    if (j == 0) *ebn2 = (se * bn) * (se * bn);
}

// CSR gather for one node; lane j sums comps (2j,2j+1) via half2 (4B/lane/nbr)
__device__ __forceinline__ void csr_agg(const __half* __restrict__ tsrc, int node,
                                        int j, float& o0, float& o1, int& deg) {
    const __half2* tp = (const __half2*)tsrc;
    int s = g_off[node], e = g_off[node + 1];
    deg = e - s;
    float a0 = 0.f, a1 = 0.f, b0 = 0.f, b1 = 0.f;
    for (int base = s; base < e; base += 32) {
        int nh = min(32, e - base);
        int idx = (j < nh) ? g_col[base + j] : 0;
        int t = 0;
        for (; t + 8 <= nh; t += 8) {
#pragma unroll
            for (int u = 0; u < 8; u += 2) {
                int sa = __shfl_sync(0xffffffffu, idx, t + u);
                int sb = __shfl_sync(0xffffffffu, idx, t + u + 1);
                float2 va = __half22float2(__ldg(tp + (size_t)sa * 32 + j));
                float2 vb = __half22float2(__ldg(tp + (size_t)sb * 32 + j));
                a0 += va.x; a1 += va.y;
                b0 += vb.x; b1 += vb.y;
            }
        }
        for (; t < nh; t++) {
            int sx = __shfl_sync(0xffffffffu, idx, t);
            float2 v = __half22float2(__ldg(tp + (size_t)sx * 32 + j));
            a0 += v.x; a1 += v.y;
        }
    }
    o0 = a0 + b0; o1 = a1 + b1;
}

// agg mean + (expmap0,proj,logmap0 folded) + relu -> unscaled u staged + t2
__device__ __forceinline__ void agg_relu_stage(const __half* __restrict__ tsrc,
                                               int iBase, int j, float2* xs,
                                               float t2[8]) {
    float h0[8], h1[8], n2[8];
#pragma unroll
    for (int q = 0; q < 8; q++) {
        int node = min(iBase + q, NN - 1);
        int deg;
        float a0, a1;
        csr_agg(tsrc, node, j, a0, a1, deg);
        float inv = __fdividef(1.f, fmaxf((float)deg, 1.f));
        h0[q] = a0 * inv;
        h1[q] = a1 * inv;
        n2[q] = h0[q] * h0[q] + h1[q] * h1[q];
    }
    float n2s = rsum8(n2, j);
    float un = sqrtf(n2s);
    float uc = fmaxf(un, MINN);
    float se = __fdividef(fast_tanh(uc), uc);
    float nn = fmaxf(se * un, MINN);
    if (nn > MAXN) { se *= __fdividef(MAXN, nn); nn = MAXN; }
    float comb = se * __fdividef(fast_atanh(nn), nn);
    float CB[8];
    bcast8(comb, CB);
#pragma unroll
    for (int q = 0; q < 8; q++) {
        float u0 = fmaxf(h0[q] * CB[q], 0.f);
        float u1 = fmaxf(h1[q] * CB[q], 0.f);
        t2[q] = u0 * u0 + u1 * u1;
        xs[j * 10 + q] = make_float2(u0, u1);
    }
    __syncwarp();
}

// load weights: Wf[t*32+j] = (W[2j][2t], W[2j][2t+1], W[2j+1][2t], W[2j+1][2t+1])
__device__ __forceinline__ void load_Wq(float4* Wf, const float* __restrict__ W,
                                        int K, int tid) {
    for (int i = tid; i < 1024; i += 256) {
        int t = i >> 5, jj = i & 31;
        int k0 = 2 * t, k1 = 2 * t + 1;
        int r0 = 2 * jj, r1 = 2 * jj + 1;
        float4 v;
        v.x = W[r0 * K + k0];
        v.y = (k1 < K) ? W[r0 * K + k1] : 0.f;
        v.z = W[r1 * K + k0];
        v.w = (k1 < K) ? W[r1 * K + k1] : 0.f;
        Wf[t * 32 + jj] = v;
    }
}

// block-local edge dtype detection
__device__ __forceinline__ int local_idx64(const int* __restrict__ e32, int* s_flag) {
    if (threadIdx.x == 0) *s_flag = 1;
    __syncthreads();
    if (threadIdx.x < 256 && e32[2 * threadIdx.x + 1] != 0) *s_flag = 0;
    __syncthreads();
    return *s_flag;
}

// per-warp chunk fetch: lane 0 atomically grabs the next 8-node chunk
__device__ __forceinline__ int warp_fetch(int* ctr, int j) {
    int v = 0;
    if (j == 0) v = atomicAdd(ctr, 1);
    return __shfl_sync(0xffffffffu, v, 0);
}

// ---------------- kernel A: poincare + layers 1..4 + logmap -> g_t ----------
__global__ void __launch_bounds__(256, 2) nodeA_kernel(
    const float* __restrict__ x,
    const float* __restrict__ W1, const float* __restrict__ b1,
    const float* __restrict__ W2, const float* __restrict__ b2,
    const float* __restrict__ W3, const float* __restrict__ b3,
    const float* __restrict__ W4, const float* __restrict__ b4) {
    extern __shared__ unsigned char smem_raw[];
    float4* Wf = (float4*)smem_raw;              // 4*1024 float4 = 64KB
    float2* xall = (float2*)(Wf + 4 * 1024);     // 8 warps * 320 float2 = 20KB
    float* eb = (float*)(xall + 8 * 320);
    float* ebn2 = eb + 256;
    int tid = threadIdx.x;

    if (blockIdx.x == 0 && tid == 0) g_ctrB = 0;   // counter for nodeB

    load_Wq(Wf,        W1, 63, tid);
    load_Wq(Wf + 1024, W2, 64, tid);
    load_Wq(Wf + 2048, W3, 64, tid);
    load_Wq(Wf + 3072, W4, 64, tid);
    int w = tid >> 5, j = tid & 31;
    if (w < 4) {
        const float* bp[4] = {b1, b2, b3, b4};
        compute_eb64(bp[w], eb + w * 64, ebn2 + w, j);
    }
    __syncthreads();

    float2* xs = xall + w * 320;

    for (int tile = blockIdx.x; tile < NODE_TILES; tile += gridDim.x) {
        int iBase = tile * 64 + w * 8;
        float t2[8], m0[8], m1[8], AA[8], BB[8];
        float c, ratio;

        // poincare map (raw; proj scale deferred into c)
        {
            float h0[8], h1[8], n2[8];
#pragma unroll
            for (int q = 0; q < 8; q++) {
                const float* xp = x + (size_t)min(iBase + q, NN - 1) * 64;
                float inv = __fdividef(1.f, xp[0] + 1.f);
                h0[q] = xp[1 + 2 * j] * inv;
                h1[q] = (j < 31) ? xp[2 + 2 * j] * inv : 0.f;
                n2[q] = h0[q] * h0[q] + h1[q] * h1[q];
            }
            stage_x8(xs, h0, h1, j);
            float n2s = rsum8(n2, j);
            float nf = fmaxf(sqrtf(n2s), MINN);
            float ps = 1.f;
            if (nf > MAXN) { ps = __fdividef(MAXN, nf); nf = MAXN; }
            c = ps;
            ratio = __fdividef(fast_atanh(nf), nf);
        }

        float2 ev;
        ev = *(const float2*)(eb + 2 * j);
        fma_block64(Wf, xs, j, m0, m1);
        layer_post(m0, m1, c, ratio, ev, ebn2[0], true, AA, BB, j);
        relu_stage(m0, m1, AA, BB, ev, xs, j, t2);
        act_pre(t2, j, c, ratio);

        ev = *(const float2*)(eb + 64 + 2 * j);
        fma_block64(Wf + 1024, xs, j, m0, m1);
        layer_post(m0, m1, c, ratio, ev, ebn2[1], true, AA, BB, j);
        relu_stage(m0, m1, AA, BB, ev, xs, j, t2);
        act_pre(t2, j, c, ratio);

        ev = *(const float2*)(eb + 128 + 2 * j);
        fma_block64(Wf + 2048, xs, j, m0, m1);
        layer_post(m0, m1, c, ratio, ev, ebn2[2], true, AA, BB, j);
        relu_stage(m0, m1, AA, BB, ev, xs, j, t2);
        act_pre(t2, j, c, ratio);

        ev = *(const float2*)(eb + 192 + 2 * j);
        fma_block64(Wf + 3072, xs, j, m0, m1);
        layer_post(m0, m1, c, ratio, ev, ebn2[3], true, AA, BB, j);
#pragma unroll
        for (int q = 0; q < 8; q++) {
            if (iBase + q < NN) {
                float v0 = AA[q] * m0[q] + BB[q] * ev.x;
                float v1 = AA[q] * m1[q] + BB[q] * ev.y;
                *((__half2*)g_t + (size_t)(iBase + q) * 32 + j) =
                    __floats2half2_rn(v0, v1);
            }
        }
    }
}

// ---------------- kernel B: agg(g_t)+act + layer5(logmap) -> g_t2 -----------
__global__ void __launch_bounds__(256, 2) nodeB_kernel(
    const float* __restrict__ W5, const float* __restrict__ b5) {
    extern __shared__ unsigned char smem_raw[];
    float4* Wf = (float4*)smem_raw;              // 1024 float4 = 16KB
    float2* xall = (float2*)(Wf + 1024);
    float* eb = (float*)(xall + 8 * 320);
    float* ebn2 = eb + 64;
    int tid = threadIdx.x;

    if (blockIdx.x == 0 && tid == 0) g_ctrC = 0;   // counter for nodeC

    load_Wq(Wf, W5, 64, tid);
    int w = tid >> 5, j = tid & 31;
    if (w == 0) compute_eb64(b5, eb, ebn2, j);
    __syncthreads();

    float2* xs = xall + w * 320;

    // per-warp dynamic chunks (8 nodes each); no block syncs after prologue
    int chunk = warp_fetch(&g_ctrB, j);
    while (chunk < NCHUNK) {
        int nextc = warp_fetch(&g_ctrB, j);   // prefetch next chunk id
        int iBase = chunk * 8;
        float t2[8], m0[8], m1[8], AA[8], BB[8];
        float c, ratio;
        agg_relu_stage(g_t, iBase, j, xs, t2);
        act_pre(t2, j, c, ratio);
        float2 ev = *(const float2*)(eb + 2 * j);
        fma_block64(Wf, xs, j, m0, m1);
        layer_post(m0, m1, c, ratio, ev, ebn2[0], true, AA, BB, j);
#pragma unroll
        for (int q = 0; q < 8; q++) {
            if (iBase + q < NN) {
                float v0 = AA[q] * m0[q] + BB[q] * ev.x;
                float v1 = AA[q] * m1[q] + BB[q] * ev.y;
                *((__half2*)g_t2 + (size_t)(iBase + q) * 32 + j) =
                    __floats2half2_rn(v0, v1);
            }
        }
        chunk = nextc;
    }
    // PDL: signal dependents (nodeC) that our g_t2 writes are done
    asm volatile("griddepcontrol.launch_dependents;");
}

// ---------------- kernel C: agg(g_t2)+act + layer6 -> out -------------------
__global__ void __launch_bounds__(256, 2) nodeC_kernel(
    const float* __restrict__ W6, const float* __restrict__ b6,
    float* __restrict__ out) {
    extern __shared__ unsigned char smem_raw[];
    float2* W6f = (float2*)smem_raw;             // 1024 float2 = 8KB
    float2* xall = W6f + 1024;
    float* eb = (float*)(xall + 8 * 320);
    float* ebn2 = eb + 32;
    int tid = threadIdx.x;
    for (int i = tid; i < 1024; i += 256) {
        int t = i >> 5, jj = i & 31;
        W6f[t * 32 + jj] = make_float2(W6[jj * 64 + 2 * t], W6[jj * 64 + 2 * t + 1]);
    }
    int w = tid >> 5, j = tid & 31;
    if (w == 0) {
        float v0 = b6[j];
        float s2 = v0 * v0;
#pragma unroll
        for (int o = 16; o > 0; o >>= 1) s2 += __shfl_xor_sync(0xffffffffu, s2, o);
        float bn = sqrtf(s2), bc = fmaxf(bn, MINN);
        float se = __fdividef(fast_tanh(bc), bc);
        eb[j] = v0 * se;
        if (j == 0) *ebn2 = (se * bn) * (se * bn);
    }
    __syncthreads();
    // PDL: prologue above is independent of nodeB; wait before touching g_t2
    asm volatile("griddepcontrol.wait;" ::: "memory");

    float2* xs = xall + w * 320;
    if (blockIdx.x == 0 && tid == 0) g_scan_done = 0;

    int chunk = warp_fetch(&g_ctrC, j);
    while (chunk < NCHUNK) {
        int nextc = warp_fetch(&g_ctrC, j);
        int iBase = chunk * 8;
        float t2[8], AA[8], BB[8];
        float c, ratio;
        agg_relu_stage(g_t2, iBase, j, xs, t2);
        act_pre(t2, j, c, ratio);
        float e0 = eb[j];
        float m[8];
        {
#pragma unroll
            for (int q = 0; q < 8; q++) m[q] = 0.f;
#pragma unroll
            for (int t = 0; t < 32; t++) {
                float2 wv = W6f[t * 32 + j];
                const float4* xt = (const float4*)(xs + t * 10);
                float4 xA = xt[0], xB = xt[1], xC = xt[2], xD = xt[3];
                m[0] = fmaf(xA.x, wv.x, fmaf(xA.y, wv.y, m[0]));
                m[1] = fmaf(xA.z, wv.x, fmaf(xA.w, wv.y, m[1]));
                m[2] = fmaf(xB.x, wv.x, fmaf(xB.y, wv.y, m[2]));
                m[3] = fmaf(xB.z, wv.x, fmaf(xB.w, wv.y, m[3]));
                m[4] = fmaf(xC.x, wv.x, fmaf(xC.y, wv.y, m[4]));
                m[5] = fmaf(xC.z, wv.x, fmaf(xC.w, wv.y, m[5]));
                m[6] = fmaf(xD.x, wv.x, fmaf(xD.y, wv.y, m[6]));
                m[7] = fmaf(xD.z, wv.x, fmaf(xD.w, wv.y, m[7]));
            }
        }
        {
            float s2[8], d[8];
#pragma unroll
            for (int q = 0; q < 8; q++) { s2[q] = m[q] * m[q]; d[q] = m[q] * e0; }
            float s2s, ds;
            rsum8x2(s2, d, j, s2s, ds);
            float ml = c * sqrtf(s2s);
            float mx = fmaxf(ml, MINN);
            float r = fast_tanh(mx * ratio);
            float sc = c * __fdividef(r, mx);
            float n1 = fmaxf(r * __fdividef(ml, mx), MINN);
            if (n1 > MAXN) { sc *= __fdividef(MAXN, n1); n1 = MAXN; }
            float xyv = sc * ds;
            float x2 = n1 * n1;
            float c1 = 1.f + 2.f * xyv + ebn2[0];
            float c2 = 1.f - x2;
            float iv = __fdividef(1.f, fmaxf(1.f + 2.f * xyv + x2 * ebn2[0], MINN));
            float q2v = iv * iv * (c1 * c1 * x2 + 2.f * c1 * c2 * xyv + c2 * c2 * ebn2[0]);
            float nf = fmaxf(sqrtf(q2v), MINN);
            float ps = 1.f;
            if (nf > MAXN) ps = __fdividef(MAXN, nf);
            float A = ps * iv * c1 * sc;
            float B = ps * iv * c2;
            bcast8(A, AA);
            bcast8(B, BB);
        }
#pragma unroll
        for (int q = 0; q < 8; q++)
            if (iBase + q < NN) out[(size_t)(iBase + q) * 32 + j] = AA[q] * m[q] + BB[q] * e0;

        // tail: zero g_cnt for the NEXT invocation (chunks cover all NN once)
        if (j < 8 && iBase + j < NN) g_cnt[iBase + j] = 0;
        chunk = nextc;
    }
}

// ---------------- CSR build ----------------
__global__ void __launch_bounds__(256) hist_kernel(const void* __restrict__ edges) {
    __shared__ int s_flag;
    int idx64 = local_idx64((const int*)edges, &s_flag);
    int i = blockIdx.x * 256 + threadIdx.x;   // over EE/2 pairs
    if (i >= EE / 2) return;
    int d0, d1;
    if (idx64) {
        longlong2 p = __ldg((const longlong2*)edges + EE / 2 + i);
        d0 = (int)p.x; d1 = (int)p.y;
    } else {
        int2 p = __ldg((const int2*)((const int*)edges + EE) + i);
        d0 = p.x; d1 = p.y;
    }
    atomicAdd(&g_cnt[d0], 1);
    atomicAdd(&g_cnt[d1], 1);
}

__global__ void __launch_bounds__(1024) scan_kernel() {
    __shared__ int sm[1024];
    __shared__ int base_s;
    int gi = blockIdx.x * 1024 + threadIdx.x;
    int v = (gi < NN) ? g_cnt[gi] : 0;
    sm[threadIdx.x] = v;
    __syncthreads();
#pragma unroll
    for (int o = 1; o < 1024; o <<= 1) {
        int t = (threadIdx.x >= o) ? sm[threadIdx.x - o] : 0;
        __syncthreads();
        sm[threadIdx.x] += t;
        __syncthreads();
    }
    int incl = sm[threadIdx.x];
    int excl = incl - v;
    if (threadIdx.x == 1023) {
        g_bsum[blockIdx.x] = incl;
        __threadfence();
        atomicAdd(&g_scan_done, 1);
    }
    if (threadIdx.x == 0) {
        while (*(volatile int*)&g_scan_done < SCAN_BLOCKS) {}
        __threadfence();
    }
    __syncthreads();
    if (threadIdx.x < 32) {
        int acc = 0;
        for (int i = (int)threadIdx.x; i < SCAN_BLOCKS; i += 32)
            if (i < (int)blockIdx.x) acc += g_bsum[i];
#pragma unroll
        for (int o = 16; o > 0; o >>= 1) acc += __shfl_xor_sync(0xffffffffu, acc, o);
        if (threadIdx.x == 0) base_s = acc;
    }
    __syncthreads();
    if (gi < NN) {
        int o = excl + base_s;
        g_off[gi] = o;
        g_cursor[gi] = o;
    }
    if (gi == 0) g_off[NN] = EE;
}

__global__ void __launch_bounds__(256) fill_kernel(const void* __restrict__ edges) {
    __shared__ int s_flag;
    int idx64 = local_idx64((const int*)edges, &s_flag);
    int i = blockIdx.x * 256 + threadIdx.x;   // over EE/2 pairs
    if (i >= EE / 2) return;
    int s0, s1, d0, d1;
    if (idx64) {
        longlong2 ps = __ldg((const longlong2*)edges + i);
        longlong2 pd = __ldg((const longlong2*)edges + EE / 2 + i);
        s0 = (int)ps.x; s1 = (int)ps.y;
        d0 = (int)pd.x; d1 = (int)pd.y;
    } else {
        int2 ps = __ldg((const int2*)edges + i);
        int2 pd = __ldg((const int2*)((const int*)edges + EE) + i);
        s0 = ps.x; s1 = ps.y;
        d0 = pd.x; d1 = pd.y;
    }
    g_col[atomicAdd(&g_cursor[d0], 1)] = s0;
    g_col[atomicAdd(&g_cursor[d1], 1)] = s1;
}

// ---------------- launch ----------------
extern "C" void kernel_launch(void* const* d_in, const int* in_sizes, int n_in,
                              void* d_out, int out_size) {
    const float* x = (const float*)d_in[0];
    const float* W1 = (const float*)d_in[1];
    const float* b1 = (const float*)d_in[2];
    const float* W2 = (const float*)d_in[3];
    const float* b2 = (const float*)d_in[4];
    const float* W3 = (const float*)d_in[5];
    const float* b3 = (const float*)d_in[6];
    const float* W4 = (const float*)d_in[7];
    const float* b4 = (const float*)d_in[8];
    const float* W5 = (const float*)d_in[9];
    const float* b5 = (const float*)d_in[10];
    const float* W6 = (const float*)d_in[11];
    const float* b6 = (const float*)d_in[12];
    const void* edges = d_in[13];
    float* out = (float*)d_out;

    const int SMEM_A = 4 * 1024 * 16 + 8 * 320 * 8 + 256 * 4 + 16;
    const int SMEM_B = 1024 * 16 + 8 * 320 * 8 + 64 * 4 + 16;
    const int SMEM_C = 1024 * 8 + 8 * 320 * 8 + 32 * 4 + 16;

    cudaFuncSetAttribute(nodeA_kernel, cudaFuncAttributeMaxDynamicSharedMemorySize, SMEM_A);
    cudaFuncSetAttribute(nodeB_kernel, cudaFuncAttributeMaxDynamicSharedMemorySize, SMEM_B);
    cudaFuncSetAttribute(nodeC_kernel, cudaFuncAttributeMaxDynamicSharedMemorySize, SMEM_C);

    const int PAIR_BLOCKS = (EE / 2 + 255) / 256;   // 3125

    cudaStream_t s2;
    cudaEvent_t ev0, evA;
    bool forked = (cudaStreamCreateWithFlags(&s2, cudaStreamNonBlocking) == cudaSuccess);
    if (forked) forked = (cudaEventCreateWithFlags(&ev0, cudaEventDisableTiming) == cudaSuccess);
    if (forked) forked = (cudaEventCreateWithFlags(&evA, cudaEventDisableTiming) == cudaSuccess);

    if (forked) {
        cudaEventRecord(ev0, 0);
        cudaStreamWaitEvent(s2, ev0, 0);
        nodeA_kernel<<<PERSIST_BLOCKS, 256, SMEM_A, s2>>>(x, W1, b1, W2, b2, W3, b3, W4, b4);
        cudaEventRecord(evA, s2);

        hist_kernel<<<PAIR_BLOCKS, 256>>>(edges);
        scan_kernel<<<SCAN_BLOCKS, 1024>>>();
        fill_kernel<<<PAIR_BLOCKS, 256>>>(edges);

        cudaStreamWaitEvent(0, evA, 0);
    } else {
        hist_kernel<<<PAIR_BLOCKS, 256>>>(edges);
        scan_kernel<<<SCAN_BLOCKS, 1024>>>();
        fill_kernel<<<PAIR_BLOCKS, 256>>>(edges);
        nodeA_kernel<<<PERSIST_BLOCKS, 256, SMEM_A>>>(x, W1, b1, W2, b2, W3, b3, W4, b4);
    }

    nodeB_kernel<<<PERSIST_BLOCKS, 256, SMEM_B>>>(W5, b5);

    // nodeC with programmatic dependent launch (prologue overlaps nodeB tail);
    // falls back to a plain launch if the attribute isn't accepted.
    {
        cudaLaunchConfig_t cfg = {};
        cfg.gridDim = dim3(PERSIST_BLOCKS);
        cfg.blockDim = dim3(256);
        cfg.dynamicSmemBytes = SMEM_C;
        cfg.stream = 0;
        cudaLaunchAttribute at[1];
        at[0].id = cudaLaunchAttributeProgrammaticStreamSerialization;
        at[0].val.programmaticStreamSerializationAllowed = 1;
        cfg.attrs = at;
        cfg.numAttrs = 1;
        if (cudaLaunchKernelEx(&cfg, nodeC_kernel, W6, b6, out) != cudaSuccess)
            nodeC_kernel<<<PERSIST_BLOCKS, 256, SMEM_C>>>(W6, b6, out);
    }
}